// round 11
// baseline (speedup 1.0000x reference)
#include <cuda_runtime.h>
#include <cuda_fp16.h>
#include <math.h>
#include <stdint.h>
#include <mma.h>
using namespace nvcuda;

// ---------------- problem constants ----------------
#define TOK   50176
#define DIM   384
#define QKVD  1152
#define FFN   1536
#define EXPD  768

// ---------------- scratch ----------------
static __device__ float  g_x  [TOK * DIM];
static __device__ __half g_xh [TOK * DIM];
static __device__ __half g_y  [TOK * DIM];
static __device__ __half g_o  [TOK * DIM];
static __device__ float  g_big[TOK * FFN];
static __device__ __half g_w  [3833856];

#define W_QKV 0
#define W_PROJ 884736
#define W_FC1 1179648
#define W_FC2 2359296
#define W_EXP 3538944

// ---------------- helpers ----------------
__device__ __forceinline__ uint32_t smem_u32(const void* p) {
    uint32_t a;
    asm("{ .reg .u64 t; cvta.to.shared.u64 t, %1; cvt.u32.u64 %0, t; }" : "=r"(a) : "l"(p));
    return a;
}
__device__ __forceinline__ void cp16(uint32_t s, const void* g) {
    asm volatile("cp.async.cg.shared.global [%0], [%1], 16;" :: "r"(s), "l"(g) : "memory");
}
#define CP_COMMIT() asm volatile("cp.async.commit_group;" ::: "memory")
#define CP_WAIT(n)  asm volatile("cp.async.wait_group %0;" :: "n"(n) : "memory")

__device__ __forceinline__ int map_row(int ridx, int shifted) {
    int n  = ridx % 49;
    int wi = (ridx / 49) & 63;
    int b  = ridx / (49 * 64);
    int r = n / 7, c = n % 7;
    int wh = wi >> 3, ww = wi & 7;
    int h = wh * 7 + r, w = ww * 7 + c;
    if (shifted) { h = (h + 3) % 56; w = (w + 3) % 56; }
    return b * 3136 + h * 56 + w;
}

__device__ __forceinline__ float warp_sum(float v) {
    #pragma unroll
    for (int o = 16; o; o >>= 1) v += __shfl_xor_sync(0xffffffffu, v, o);
    return v;
}
__device__ __forceinline__ float gelu(float v) {
    return 0.5f * v * (1.f + erff(v * 0.7071067811865476f));
}

// ---------------- fp16 wmma GEMM (unchanged from round 10) ----------------
#define ASTR 72
#define BSTR 136
#define A_STAGE (128 * ASTR)
#define B_STAGE (64 * BSTR)
#define STG (A_STAGE + B_STAGE)
#define OSTR 132

__global__ __launch_bounds__(128, 2)
void gemm_fp16(const __half* __restrict__ A, const __half* __restrict__ W,
               const float* __restrict__ bias, void* __restrict__ Cv,
               __half* __restrict__ mirror, const float* __restrict__ resid,
               int K, int Nc, int epilogue, int shifted, int out_half) {
    extern __shared__ __align__(16) char smraw[];
    __half* smh = (__half*)smraw;
    float*  smf = (float*)smraw;
    int tid = threadIdx.x;
    int wid = tid >> 5;
    int wm = (wid & 1) * 64;
    int wn = (wid >> 1) * 64;
    int rowBase = blockIdx.y * 128;
    int colBase = blockIdx.x * 128;
    int nk = K >> 6;

    wmma::fragment<wmma::accumulator, 16, 16, 16, float> acc[4][4];
    #pragma unroll
    for (int i = 0; i < 4; i++)
        #pragma unroll
        for (int j = 0; j < 4; j++) wmma::fill_fragment(acc[i][j], 0.f);

    #define STAGE_LOAD(kt, buf) do {                                              \
        __half* As_ = smh + (buf) * STG;                                          \
        __half* Bs_ = As_ + A_STAGE;                                              \
        uint32_t as_ = smem_u32(As_), bs_ = smem_u32(Bs_);                        \
        int kg_ = (kt) * 64;                                                      \
        _Pragma("unroll")                                                         \
        for (int l = 0; l < 8; l++) {                                             \
            int c = tid + l * 128;                                                \
            int r = c >> 3, q = (c & 7) * 8;                                      \
            cp16(as_ + (uint32_t)(r * ASTR + q) * 2,                              \
                 A + (size_t)(rowBase + r) * K + kg_ + q);                        \
            int kr = c >> 4, nq = (c & 15) * 8;                                   \
            cp16(bs_ + (uint32_t)(kr * BSTR + nq) * 2,                            \
                 W + (size_t)(kg_ + kr) * Nc + colBase + nq);                     \
        }                                                                         \
    } while (0)

    STAGE_LOAD(0, 0); CP_COMMIT();
    STAGE_LOAD(1, 1); CP_COMMIT();

    for (int kt = 0; kt < nk; kt++) {
        if (kt + 1 < nk) { CP_WAIT(1); } else { CP_WAIT(0); }
        __syncthreads();
        if (kt + 2 < nk) { STAGE_LOAD(kt + 2, (kt + 2) % 3); CP_COMMIT(); }

        const __half* As = smh + (kt % 3) * STG;
        const __half* Bs = As + A_STAGE;
        #pragma unroll
        for (int k16 = 0; k16 < 4; k16++) {
            wmma::fragment<wmma::matrix_a, 16, 16, 16, __half, wmma::row_major> af[4];
            wmma::fragment<wmma::matrix_b, 16, 16, 16, __half, wmma::row_major> bf[4];
            #pragma unroll
            for (int i = 0; i < 4; i++)
                wmma::load_matrix_sync(af[i], As + (wm + i * 16) * ASTR + k16 * 16, ASTR);
            #pragma unroll
            for (int j = 0; j < 4; j++)
                wmma::load_matrix_sync(bf[j], Bs + (k16 * 16) * BSTR + wn + j * 16, BSTR);
            #pragma unroll
            for (int i = 0; i < 4; i++)
                #pragma unroll
                for (int j = 0; j < 4; j++)
                    wmma::mma_sync(acc[i][j], af[i], bf[j], acc[i][j]);
        }
    }
    __syncthreads();

    #pragma unroll
    for (int i = 0; i < 4; i++)
        #pragma unroll
        for (int j = 0; j < 4; j++)
            wmma::store_matrix_sync(smf + (wm + i * 16) * OSTR + wn + j * 16,
                                    acc[i][j], OSTR, wmma::mem_row_major);
    __syncthreads();

    if (epilogue <= 1) {
        if (out_half) {
            __half* C = (__half*)Cv;
            #pragma unroll 4
            for (int e = 0; e < 32; e++) {
                int idx = tid + e * 128;
                int r = idx >> 5, c4 = (idx & 31) * 4;
                int gc = colBase + c4;
                float4 v = *(const float4*)(smf + r * OSTR + c4);
                if (bias) {
                    float4 bv = *(const float4*)(bias + gc);
                    v.x += bv.x; v.y += bv.y; v.z += bv.z; v.w += bv.w;
                }
                if (epilogue == 1) {
                    v.x = gelu(v.x); v.y = gelu(v.y); v.z = gelu(v.z); v.w = gelu(v.w);
                }
                __half2 h0 = __floats2half2_rn(v.x, v.y);
                __half2 h1 = __floats2half2_rn(v.z, v.w);
                __half2* cp = (__half2*)(C + (size_t)(rowBase + r) * Nc + gc);
                cp[0] = h0; cp[1] = h1;
            }
        } else {
            float* C = (float*)Cv;
            #pragma unroll 4
            for (int e = 0; e < 32; e++) {
                int idx = tid + e * 128;
                int r = idx >> 5, c4 = (idx & 31) * 4;
                int gc = colBase + c4;
                float4 v = *(const float4*)(smf + r * OSTR + c4);
                if (bias) {
                    float4 bv = *(const float4*)(bias + gc);
                    v.x += bv.x; v.y += bv.y; v.z += bv.z; v.w += bv.w;
                }
                *(float4*)(C + (size_t)(rowBase + r) * Nc + gc) = v;
            }
        }
    } else {
        float* C = (float*)Cv;
        #pragma unroll 4
        for (int e = 0; e < 32; e++) {
            int idx = tid + e * 128;
            int r = idx >> 5, c4 = (idx & 31) * 4;
            int gr = rowBase + r, gc = colBase + c4;
            float4 v = *(const float4*)(smf + r * OSTR + c4);
            float4 bv = *(const float4*)(bias + gc);
            v.x += bv.x; v.y += bv.y; v.z += bv.z; v.w += bv.w;
            int orow = (epilogue == 2) ? map_row(gr, shifted) : gr;
            size_t off = (size_t)orow * Nc + gc;
            float4 rv = *(const float4*)(resid + off);
            v.x += rv.x; v.y += rv.y; v.z += rv.z; v.w += rv.w;
            *(float4*)(C + off) = v;
            if (epilogue == 3) {
                __half2* mp = (__half2*)(mirror + off);
                mp[0] = __floats2half2_rn(v.x, v.y);
                mp[1] = __floats2half2_rn(v.z, v.w);
            }
        }
    }
}

// ---------------- weight fp32 -> fp16 ----------------
__global__ void tohalf_kernel(const float4* __restrict__ in, __half* __restrict__ out, int n4) {
    int i = blockIdx.x * blockDim.x + threadIdx.x;
    if (i < n4) {
        float4 v = in[i];
        __half2* o = (__half2*)(out + i * 4);
        o[0] = __floats2half2_rn(v.x, v.y);
        o[1] = __floats2half2_rn(v.z, v.w);
    }
}

// ---------------- LayerNorm over 384: 1 warp per row ----------------
__global__ __launch_bounds__(256)
void ln384_kernel(const float* __restrict__ src, __half* __restrict__ dst,
                  const float* __restrict__ g, const float* __restrict__ b,
                  int mode) {
    int row = blockIdx.x * 8 + (threadIdx.x >> 5);
    int lane = threadIdx.x & 31;
    int t = (mode == 0) ? row : map_row(row, mode == 2);
    const float* sp = src + (size_t)t * DIM;
    float v[12];
    float s = 0.f;
    #pragma unroll
    for (int e = 0; e < 12; e++) { v[e] = sp[lane + e * 32]; s += v[e]; }
    float m = warp_sum(s) * (1.f / 384.f);
    float vs = 0.f;
    #pragma unroll
    for (int e = 0; e < 12; e++) { v[e] -= m; vs += v[e] * v[e]; }
    float inv = rsqrtf(warp_sum(vs) * (1.f / 384.f) + 1e-5f);
    __half* dp = dst + (size_t)row * DIM;
    #pragma unroll
    for (int e = 0; e < 12; e++) {
        int c = lane + e * 32;
        dp[c] = __float2half(v[e] * inv * g[c] + b[c]);
    }
}

// ---------------- HMMA windowed attention: 1 block per (window, head), 4 warps ----
// Q/K/V padded 49->64 rows; QK^T and PV on tensor cores, softmax fp32.
__global__ __launch_bounds__(128)
void attn_mma_kernel(const __half* __restrict__ qkv, __half* __restrict__ o,
                     const float* __restrict__ rpb, int shifted) {
    __shared__ __half qs[64 * 40];
    __shared__ __half ks[64 * 40];
    __shared__ __half vsm[64 * 40];
    __shared__ float  ss[64 * 68];     // scores, later reused (ld 36) for output
    __shared__ __half ps[64 * 72];
    __shared__ float  rsum[64];

    int head = blockIdx.x % 12;
    int win  = blockIdx.x / 12;
    int wi = win & 63;
    int wh = wi >> 3, ww = wi & 7;
    int base = win * 49;
    int tid = threadIdx.x;
    int wid = tid >> 5;

    const float sc = 0.17677669529663687f;
    const __half2 z2 = __float2half2_rn(0.f);

    // load q (scaled), k, v; zero pad rows
    for (int idx = tid; idx < 64 * 16; idx += 128) {
        int j = idx >> 4, d2 = (idx & 15) * 2;
        int off = j * 40 + d2;
        if (j < 49) {
            size_t ro = (size_t)(base + j) * QKVD + head * 32 + d2;
            __half2 qv = *(const __half2*)(qkv + ro);
            float2 qf = __half22float2(qv);
            *(__half2*)(qs + off)  = __floats2half2_rn(qf.x * sc, qf.y * sc);
            *(__half2*)(ks + off)  = *(const __half2*)(qkv + ro + 384);
            *(__half2*)(vsm + off) = *(const __half2*)(qkv + ro + 768);
        } else {
            *(__half2*)(qs + off)  = z2;
            *(__half2*)(ks + off)  = z2;
            *(__half2*)(vsm + off) = z2;
        }
    }
    // zero pad cols 32..39
    for (int idx = tid; idx < 64 * 4; idx += 128) {
        int j = idx >> 2, d2 = 32 + (idx & 3) * 2;
        int off = j * 40 + d2;
        *(__half2*)(qs + off)  = z2;
        *(__half2*)(ks + off)  = z2;
        *(__half2*)(vsm + off) = z2;
    }
    __syncthreads();

    // QK^T: warp wid -> rows [16w,16w+16), all 64 cols
    {
        wmma::fragment<wmma::accumulator, 16, 16, 16, float> sacc[4];
        #pragma unroll
        for (int n = 0; n < 4; n++) wmma::fill_fragment(sacc[n], 0.f);
        #pragma unroll
        for (int k16 = 0; k16 < 2; k16++) {
            wmma::fragment<wmma::matrix_a, 16, 16, 16, __half, wmma::row_major> aq;
            wmma::load_matrix_sync(aq, qs + (wid * 16) * 40 + k16 * 16, 40);
            #pragma unroll
            for (int n = 0; n < 4; n++) {
                wmma::fragment<wmma::matrix_b, 16, 16, 16, __half, wmma::col_major> bk;
                wmma::load_matrix_sync(bk, ks + (n * 16) * 40 + k16 * 16, 40);
                wmma::mma_sync(sacc[n], aq, bk, sacc[n]);
            }
        }
        #pragma unroll
        for (int n = 0; n < 4; n++)
            wmma::store_matrix_sync(ss + (wid * 16) * 68 + n * 16, sacc[n], 68,
                                    wmma::mem_row_major);
    }
    __syncthreads();

    // softmax: thread t<64 handles row t
    if (tid < 64) {
        int i = tid;
        if (i < 49) {
            int ri = i / 7, ci = i % 7;
            int lab_i = 0;
            if (shifted) {
                int hh = wh * 7 + ri, wc = ww * 7 + ci;
                int gh = hh < 49 ? 0 : (hh < 53 ? 1 : 2);
                int gw = wc < 49 ? 0 : (wc < 53 ? 1 : 2);
                lab_i = gh * 3 + gw;
            }
            float sum = 0.f;
            for (int j = 0; j < 49; j++) {
                float s = ss[i * 68 + j];
                int rj = j / 7, cj = j % 7;
                int rpi = (ri - rj + 6) * 13 + (ci - cj + 6);
                s += rpb[rpi * 12 + head];
                if (shifted) {
                    int hh = wh * 7 + rj, wc = ww * 7 + cj;
                    int gh = hh < 49 ? 0 : (hh < 53 ? 1 : 2);
                    int gw = wc < 49 ? 0 : (wc < 53 ? 1 : 2);
                    if (gh * 3 + gw != lab_i) s -= 100.0f;
                }
                __half eh = __float2half(expf(s));
                ps[i * 72 + j] = eh;
                sum += __half2float(eh);   // consistent with fp16 weights used in PV
            }
            for (int j = 49; j < 64; j++) ps[i * 72 + j] = __float2half(0.f);
            rsum[i] = 1.0f / sum;
        } else {
            for (int j = 0; j < 64; j++) ps[i * 72 + j] = __float2half(0.f);
            rsum[i] = 0.f;
        }
    }
    __syncthreads();

    // PV: warp wid -> rows [16w,16w+16) x 32 cols; reuse ss (ld 36) as output
    {
        wmma::fragment<wmma::accumulator, 16, 16, 16, float> oacc[2];
        #pragma unroll
        for (int n = 0; n < 2; n++) wmma::fill_fragment(oacc[n], 0.f);
        #pragma unroll
        for (int k16 = 0; k16 < 4; k16++) {
            wmma::fragment<wmma::matrix_a, 16, 16, 16, __half, wmma::row_major> ap;
            wmma::load_matrix_sync(ap, ps + (wid * 16) * 72 + k16 * 16, 72);
            #pragma unroll
            for (int n = 0; n < 2; n++) {
                wmma::fragment<wmma::matrix_b, 16, 16, 16, __half, wmma::row_major> bv;
                wmma::load_matrix_sync(bv, vsm + (k16 * 16) * 40 + n * 16, 40);
                wmma::mma_sync(oacc[n], ap, bv, oacc[n]);
            }
        }
        #pragma unroll
        for (int n = 0; n < 2; n++)
            wmma::store_matrix_sync(ss + (wid * 16) * 36 + n * 16, oacc[n], 36,
                                    wmma::mem_row_major);
    }
    __syncthreads();

    // epilogue: rows < 49, 32 cols
    for (int idx = tid; idx < 49 * 16; idx += 128) {
        int i = idx >> 4, d2 = (idx & 15) * 2;
        float inv = rsum[i];
        float v0 = ss[i * 36 + d2]     * inv;
        float v1 = ss[i * 36 + d2 + 1] * inv;
        *(__half2*)(o + (size_t)(base + i) * DIM + head * 32 + d2) =
            __floats2half2_rn(v0, v1);
    }
}

// ---------------- PatchExpand pixel-shuffle + LN over 192: 1 warp per token ----------
__global__ __launch_bounds__(256)
void expand_ln_kernel(const float* __restrict__ e, float* __restrict__ out,
                      const float* __restrict__ g, const float* __restrict__ b) {
    int tt = blockIdx.x * 8 + (threadIdx.x >> 5);
    int lane = threadIdx.x & 31;
    int bb = tt / 12544;
    int rem = tt % 12544;
    int oh = rem / 112, ow = rem % 112;
    int h = oh >> 1, p = oh & 1, w = ow >> 1, q = ow & 1;
    int erow = bb * 3136 + h * 56 + w;
    const float* sp = e + (size_t)erow * EXPD + (p * 2 + q) * 192;
    float v[6];
    float s = 0.f;
    #pragma unroll
    for (int k = 0; k < 6; k++) { v[k] = sp[lane + k * 32]; s += v[k]; }
    float m = warp_sum(s) * (1.f / 192.f);
    float vs = 0.f;
    #pragma unroll
    for (int k = 0; k < 6; k++) { v[k] -= m; vs += v[k] * v[k]; }
    float inv = rsqrtf(warp_sum(vs) * (1.f / 192.f) + 1e-5f);
    float* dp = out + (size_t)tt * 192;
    #pragma unroll
    for (int k = 0; k < 6; k++) {
        int c = lane + k * 32;
        dp[c] = v[k] * inv * g[c] + b[c];
    }
}

// ---------------- host orchestration ----------------
extern "C" void kernel_launch(void* const* d_in, const int* in_sizes, int n_in,
                              void* d_out, int out_size) {
    const float* x    = (const float*)d_in[0];
    const float* n1g  = (const float*)d_in[1];
    const float* n1b  = (const float*)d_in[2];
    const float* qkvw = (const float*)d_in[3];
    const float* qkvb = (const float*)d_in[4];
    const float* rpb  = (const float*)d_in[5];
    const float* pw   = (const float*)d_in[6];
    const float* pb   = (const float*)d_in[7];
    const float* n2g  = (const float*)d_in[8];
    const float* n2b  = (const float*)d_in[9];
    const float* f1w  = (const float*)d_in[10];
    const float* f1b  = (const float*)d_in[11];
    const float* f2w  = (const float*)d_in[12];
    const float* f2b  = (const float*)d_in[13];
    const float* ew   = (const float*)d_in[14];
    const float* eg   = (const float*)d_in[15];
    const float* ebv  = (const float*)d_in[16];

    float *xb, *bigb;
    __half *xh, *yh, *oh, *wh;
    cudaGetSymbolAddress((void**)&xb,   g_x);
    cudaGetSymbolAddress((void**)&xh,   g_xh);
    cudaGetSymbolAddress((void**)&yh,   g_y);
    cudaGetSymbolAddress((void**)&oh,   g_o);
    cudaGetSymbolAddress((void**)&bigb, g_big);
    cudaGetSymbolAddress((void**)&wh,   g_w);

    static int smem_set = 0;
    const int GEMM_SMEM = 3 * STG * sizeof(__half);   // 107520 B
    if (!smem_set) {
        cudaFuncSetAttribute(gemm_fp16,
                             cudaFuncAttributeMaxDynamicSharedMemorySize, GEMM_SMEM);
        smem_set = 1;
    }

    // launches ordered so ncu (-s 5 -c 1) captures the qkv GEMM
    tohalf_kernel<<<(884736/4 + 255)/256, 256>>>((const float4*)qkvw, wh + W_QKV, 884736/4);
    tohalf_kernel<<<(294912/4 + 255)/256, 256>>>((const float4*)pw,   wh + W_PROJ, 294912/4);
    tohalf_kernel<<<(1179648/4 + 255)/256, 256>>>((const float4*)f1w, wh + W_FC1, 1179648/4);
    tohalf_kernel<<<(1179648/4 + 255)/256, 256>>>((const float4*)f2w, wh + W_FC2, 1179648/4);

    const int MB = TOK / 128;
    for (int i = 0; i < 2; i++) {
        int sh = i;
        const float* res = (i == 0) ? x : xb;
        ln384_kernel<<<TOK / 8, 256>>>(res, yh, n1g + i * DIM, n1b + i * DIM, sh ? 2 : 1);
        gemm_fp16<<<dim3(QKVD / 128, MB), 128, GEMM_SMEM>>>(
            yh, wh + W_QKV + (size_t)i * DIM * QKVD, qkvb + i * QKVD,
            bigb, nullptr, nullptr, DIM, QKVD, 0, 0, 1);
        attn_mma_kernel<<<1024 * 12, 128>>>((const __half*)bigb, oh, rpb + i * 169 * 12, sh);
        gemm_fp16<<<dim3(DIM / 128, MB), 128, GEMM_SMEM>>>(
            oh, wh + W_PROJ + (size_t)i * DIM * DIM, pb + i * DIM,
            xb, nullptr, res, DIM, DIM, 2, sh, 0);
        ln384_kernel<<<TOK / 8, 256>>>(xb, yh, n2g + i * DIM, n2b + i * DIM, 0);
        gemm_fp16<<<dim3(FFN / 128, MB), 128, GEMM_SMEM>>>(
            yh, wh + W_FC1 + (size_t)i * DIM * FFN, f1b + i * FFN,
            bigb, nullptr, nullptr, DIM, FFN, 1, 0, 1);
        gemm_fp16<<<dim3(DIM / 128, MB), 128, GEMM_SMEM>>>(
            (const __half*)bigb, wh + W_FC2 + (size_t)i * FFN * DIM, f2b + i * DIM,
            xb, xh, xb, FFN, DIM, 3, 0, 0);
    }

    tohalf_kernel<<<(294912/4 + 255)/256, 256>>>((const float4*)ew, wh + W_EXP, 294912/4);
    gemm_fp16<<<dim3(EXPD / 128, MB), 128, GEMM_SMEM>>>(
        xh, wh + W_EXP, nullptr, bigb, nullptr, nullptr, DIM, EXPD, 0, 0, 0);
    expand_ln_kernel<<<TOK * 4 / 8, 256>>>(bigb, (float*)d_out, eg, ebv);
}

// round 12
// speedup vs baseline: 1.0483x; 1.0483x over previous
#include <cuda_runtime.h>
#include <cuda_fp16.h>
#include <math.h>
#include <stdint.h>
#include <mma.h>
using namespace nvcuda;

// ---------------- problem constants ----------------
#define TOK   50176
#define DIM   384
#define QKVD  1152
#define FFN   1536
#define EXPD  768

// ---------------- scratch ----------------
static __device__ float  g_x  [TOK * DIM];
static __device__ __half g_xh [TOK * DIM];
static __device__ __half g_y  [TOK * DIM];
static __device__ __half g_o  [TOK * DIM];
static __device__ float  g_big[TOK * FFN];
static __device__ __half g_w  [3833856];

#define W_QKV 0
#define W_PROJ 884736
#define W_FC1 1179648
#define W_FC2 2359296
#define W_EXP 3538944

// ---------------- helpers ----------------
__device__ __forceinline__ uint32_t smem_u32(const void* p) {
    uint32_t a;
    asm("{ .reg .u64 t; cvta.to.shared.u64 t, %1; cvt.u32.u64 %0, t; }" : "=r"(a) : "l"(p));
    return a;
}
__device__ __forceinline__ void cp16(uint32_t s, const void* g) {
    asm volatile("cp.async.cg.shared.global [%0], [%1], 16;" :: "r"(s), "l"(g) : "memory");
}
#define CP_COMMIT() asm volatile("cp.async.commit_group;" ::: "memory")
#define CP_WAIT(n)  asm volatile("cp.async.wait_group %0;" :: "n"(n) : "memory")

__device__ __forceinline__ int map_row(int ridx, int shifted) {
    int n  = ridx % 49;
    int wi = (ridx / 49) & 63;
    int b  = ridx / (49 * 64);
    int r = n / 7, c = n % 7;
    int wh = wi >> 3, ww = wi & 7;
    int h = wh * 7 + r, w = ww * 7 + c;
    if (shifted) { h = (h + 3) % 56; w = (w + 3) % 56; }
    return b * 3136 + h * 56 + w;
}

__device__ __forceinline__ float warp_sum(float v) {
    #pragma unroll
    for (int o = 16; o; o >>= 1) v += __shfl_xor_sync(0xffffffffu, v, o);
    return v;
}
__device__ __forceinline__ float gelu(float v) {
    return 0.5f * v * (1.f + erff(v * 0.7071067811865476f));
}

// ---------------- fp16 wmma GEMM (round-10 config, unchanged) ----------------
#define ASTR 72
#define BSTR 136
#define A_STAGE (128 * ASTR)
#define B_STAGE (64 * BSTR)
#define STG (A_STAGE + B_STAGE)
#define OSTR 132

__global__ __launch_bounds__(128, 2)
void gemm_fp16(const __half* __restrict__ A, const __half* __restrict__ W,
               const float* __restrict__ bias, void* __restrict__ Cv,
               __half* __restrict__ mirror, const float* __restrict__ resid,
               int K, int Nc, int epilogue, int shifted, int out_half) {
    extern __shared__ __align__(16) char smraw[];
    __half* smh = (__half*)smraw;
    float*  smf = (float*)smraw;
    int tid = threadIdx.x;
    int wid = tid >> 5;
    int wm = (wid & 1) * 64;
    int wn = (wid >> 1) * 64;
    int rowBase = blockIdx.y * 128;
    int colBase = blockIdx.x * 128;
    int nk = K >> 6;

    wmma::fragment<wmma::accumulator, 16, 16, 16, float> acc[4][4];
    #pragma unroll
    for (int i = 0; i < 4; i++)
        #pragma unroll
        for (int j = 0; j < 4; j++) wmma::fill_fragment(acc[i][j], 0.f);

    #define STAGE_LOAD(kt, buf) do {                                              \
        __half* As_ = smh + (buf) * STG;                                          \
        __half* Bs_ = As_ + A_STAGE;                                              \
        uint32_t as_ = smem_u32(As_), bs_ = smem_u32(Bs_);                        \
        int kg_ = (kt) * 64;                                                      \
        _Pragma("unroll")                                                         \
        for (int l = 0; l < 8; l++) {                                             \
            int c = tid + l * 128;                                                \
            int r = c >> 3, q = (c & 7) * 8;                                      \
            cp16(as_ + (uint32_t)(r * ASTR + q) * 2,                              \
                 A + (size_t)(rowBase + r) * K + kg_ + q);                        \
            int kr = c >> 4, nq = (c & 15) * 8;                                   \
            cp16(bs_ + (uint32_t)(kr * BSTR + nq) * 2,                            \
                 W + (size_t)(kg_ + kr) * Nc + colBase + nq);                     \
        }                                                                         \
    } while (0)

    STAGE_LOAD(0, 0); CP_COMMIT();
    STAGE_LOAD(1, 1); CP_COMMIT();

    for (int kt = 0; kt < nk; kt++) {
        if (kt + 1 < nk) { CP_WAIT(1); } else { CP_WAIT(0); }
        __syncthreads();
        if (kt + 2 < nk) { STAGE_LOAD(kt + 2, (kt + 2) % 3); CP_COMMIT(); }

        const __half* As = smh + (kt % 3) * STG;
        const __half* Bs = As + A_STAGE;
        #pragma unroll
        for (int k16 = 0; k16 < 4; k16++) {
            wmma::fragment<wmma::matrix_a, 16, 16, 16, __half, wmma::row_major> af[4];
            wmma::fragment<wmma::matrix_b, 16, 16, 16, __half, wmma::row_major> bf[4];
            #pragma unroll
            for (int i = 0; i < 4; i++)
                wmma::load_matrix_sync(af[i], As + (wm + i * 16) * ASTR + k16 * 16, ASTR);
            #pragma unroll
            for (int j = 0; j < 4; j++)
                wmma::load_matrix_sync(bf[j], Bs + (k16 * 16) * BSTR + wn + j * 16, BSTR);
            #pragma unroll
            for (int i = 0; i < 4; i++)
                #pragma unroll
                for (int j = 0; j < 4; j++)
                    wmma::mma_sync(acc[i][j], af[i], bf[j], acc[i][j]);
        }
    }
    __syncthreads();

    #pragma unroll
    for (int i = 0; i < 4; i++)
        #pragma unroll
        for (int j = 0; j < 4; j++)
            wmma::store_matrix_sync(smf + (wm + i * 16) * OSTR + wn + j * 16,
                                    acc[i][j], OSTR, wmma::mem_row_major);
    __syncthreads();

    if (epilogue <= 1) {
        if (out_half) {
            __half* C = (__half*)Cv;
            #pragma unroll 4
            for (int e = 0; e < 32; e++) {
                int idx = tid + e * 128;
                int r = idx >> 5, c4 = (idx & 31) * 4;
                int gc = colBase + c4;
                float4 v = *(const float4*)(smf + r * OSTR + c4);
                if (bias) {
                    float4 bv = *(const float4*)(bias + gc);
                    v.x += bv.x; v.y += bv.y; v.z += bv.z; v.w += bv.w;
                }
                if (epilogue == 1) {
                    v.x = gelu(v.x); v.y = gelu(v.y); v.z = gelu(v.z); v.w = gelu(v.w);
                }
                __half2 h0 = __floats2half2_rn(v.x, v.y);
                __half2 h1 = __floats2half2_rn(v.z, v.w);
                __half2* cp = (__half2*)(C + (size_t)(rowBase + r) * Nc + gc);
                cp[0] = h0; cp[1] = h1;
            }
        } else {
            float* C = (float*)Cv;
            #pragma unroll 4
            for (int e = 0; e < 32; e++) {
                int idx = tid + e * 128;
                int r = idx >> 5, c4 = (idx & 31) * 4;
                int gc = colBase + c4;
                float4 v = *(const float4*)(smf + r * OSTR + c4);
                if (bias) {
                    float4 bv = *(const float4*)(bias + gc);
                    v.x += bv.x; v.y += bv.y; v.z += bv.z; v.w += bv.w;
                }
                *(float4*)(C + (size_t)(rowBase + r) * Nc + gc) = v;
            }
        }
    } else {
        float* C = (float*)Cv;
        #pragma unroll 4
        for (int e = 0; e < 32; e++) {
            int idx = tid + e * 128;
            int r = idx >> 5, c4 = (idx & 31) * 4;
            int gr = rowBase + r, gc = colBase + c4;
            float4 v = *(const float4*)(smf + r * OSTR + c4);
            float4 bv = *(const float4*)(bias + gc);
            v.x += bv.x; v.y += bv.y; v.z += bv.z; v.w += bv.w;
            int orow = (epilogue == 2) ? map_row(gr, shifted) : gr;
            size_t off = (size_t)orow * Nc + gc;
            float4 rv = *(const float4*)(resid + off);
            v.x += rv.x; v.y += rv.y; v.z += rv.z; v.w += rv.w;
            *(float4*)(C + off) = v;
            if (epilogue == 3) {
                __half2* mp = (__half2*)(mirror + off);
                mp[0] = __floats2half2_rn(v.x, v.y);
                mp[1] = __floats2half2_rn(v.z, v.w);
            }
        }
    }
}

// ---------------- weight fp32 -> fp16 ----------------
__global__ void tohalf_kernel(const float4* __restrict__ in, __half* __restrict__ out, int n4) {
    int i = blockIdx.x * blockDim.x + threadIdx.x;
    if (i < n4) {
        float4 v = in[i];
        __half2* o = (__half2*)(out + i * 4);
        o[0] = __floats2half2_rn(v.x, v.y);
        o[1] = __floats2half2_rn(v.z, v.w);
    }
}

// ---------------- LayerNorm over 384: 1 warp per row, float4 I/O ----------------
__global__ __launch_bounds__(256)
void ln384_kernel(const float* __restrict__ src, __half* __restrict__ dst,
                  const float* __restrict__ g, const float* __restrict__ b,
                  int mode) {
    int row = blockIdx.x * 8 + (threadIdx.x >> 5);
    int lane = threadIdx.x & 31;
    int t = (mode == 0) ? row : map_row(row, mode == 2);
    const float4* sp = (const float4*)(src + (size_t)t * DIM);
    float4 v[3];
    float s = 0.f;
    #pragma unroll
    for (int e = 0; e < 3; e++) {
        v[e] = sp[lane + e * 32];
        s += v[e].x + v[e].y + v[e].z + v[e].w;
    }
    float m = warp_sum(s) * (1.f / 384.f);
    float vs = 0.f;
    #pragma unroll
    for (int e = 0; e < 3; e++) {
        v[e].x -= m; v[e].y -= m; v[e].z -= m; v[e].w -= m;
        vs += v[e].x * v[e].x + v[e].y * v[e].y + v[e].z * v[e].z + v[e].w * v[e].w;
    }
    float inv = rsqrtf(warp_sum(vs) * (1.f / 384.f) + 1e-5f);
    __half* dp = dst + (size_t)row * DIM;
    #pragma unroll
    for (int e = 0; e < 3; e++) {
        int c4 = (lane + e * 32) * 4;
        float4 gv = *(const float4*)(g + c4);
        float4 bv = *(const float4*)(b + c4);
        float o0 = v[e].x * inv * gv.x + bv.x;
        float o1 = v[e].y * inv * gv.y + bv.y;
        float o2 = v[e].z * inv * gv.z + bv.z;
        float o3 = v[e].w * inv * gv.w + bv.w;
        __half2* hp = (__half2*)(dp + c4);
        hp[0] = __floats2half2_rn(o0, o1);
        hp[1] = __floats2half2_rn(o2, o3);
    }
}

// ---------------- windowed attention: single-pass, 2 heads / 128-thread block ----
// smem bias table + precomputed mask labels + __expf + unrolled 7x7 j-loop
__global__ void attn_kernel(const __half* __restrict__ qkv, __half* __restrict__ o,
                            const float* __restrict__ rpb, int shifted) {
    __shared__ float4 ksm[2][49][8];
    __shared__ float4 vsm[2][49][8];
    __shared__ float  bias_s[2][169];
    __shared__ int    lab_s[49];
    int pair = blockIdx.x;
    int win  = pair / 6;
    int hp   = (pair % 6) * 2;
    int sub  = threadIdx.x >> 6;
    int t    = threadIdx.x & 63;
    int head = hp + sub;
    int wi = win & 63;
    int wh = wi >> 3, ww = wi & 7;
    int base = win * 49;

    for (int idx = t; idx < 49 * 8; idx += 64) {
        int j = idx >> 3, d4 = idx & 7;
        size_t ro = (size_t)(base + j) * QKVD + head * 32 + d4 * 4;
        const __half2* kp = (const __half2*)(qkv + ro + 384);
        const __half2* vp = (const __half2*)(qkv + ro + 768);
        float2 k0 = __half22float2(kp[0]), k1 = __half22float2(kp[1]);
        float2 w0 = __half22float2(vp[0]), w1 = __half22float2(vp[1]);
        ksm[sub][j][d4] = make_float4(k0.x, k0.y, k1.x, k1.y);
        vsm[sub][j][d4] = make_float4(w0.x, w0.y, w1.x, w1.y);
    }
    for (int idx = t; idx < 169; idx += 64)
        bias_s[sub][idx] = rpb[idx * 12 + head];
    if (sub == 0 && t < 49) {
        int rj = t / 7, cj = t % 7;
        int hh = wh * 7 + rj, wc = ww * 7 + cj;
        int gh = hh < 49 ? 0 : (hh < 53 ? 1 : 2);
        int gw = wc < 49 ? 0 : (wc < 53 ? 1 : 2);
        lab_s[t] = gh * 3 + gw;
    }
    __syncthreads();

    if (t < 49) {
        int i = t, ri = i / 7, ci = i % 7;
        float4 q[8];
        const __half2* qp = (const __half2*)(qkv + (size_t)(base + i) * QKVD + head * 32);
        #pragma unroll
        for (int d4 = 0; d4 < 8; d4++) {
            float2 a = __half22float2(qp[d4 * 2]), b = __half22float2(qp[d4 * 2 + 1]);
            const float sc = 0.17677669529663687f;
            q[d4] = make_float4(a.x * sc, a.y * sc, b.x * sc, b.y * sc);
        }
        int lab_i = lab_s[i];

        float sum = 0.f;
        float4 accv[8];
        #pragma unroll
        for (int d4 = 0; d4 < 8; d4++) accv[d4] = make_float4(0.f, 0.f, 0.f, 0.f);

        for (int rj = 0; rj < 7; rj++) {
            int rbase = (ri - rj + 6) * 13 + ci + 6;
            #pragma unroll
            for (int cj = 0; cj < 7; cj++) {
                int j = rj * 7 + cj;
                float s = 0.f;
                #pragma unroll
                for (int d4 = 0; d4 < 8; d4++) {
                    float4 kv = ksm[sub][j][d4];
                    s += q[d4].x * kv.x + q[d4].y * kv.y + q[d4].z * kv.z + q[d4].w * kv.w;
                }
                s += bias_s[sub][rbase - cj];
                if (shifted && lab_s[j] != lab_i) s -= 100.0f;
                float e = __expf(s);
                sum += e;
                #pragma unroll
                for (int d4 = 0; d4 < 8; d4++) {
                    float4 vv = vsm[sub][j][d4];
                    accv[d4].x += e * vv.x; accv[d4].y += e * vv.y;
                    accv[d4].z += e * vv.z; accv[d4].w += e * vv.w;
                }
            }
        }
        float inv = 1.0f / sum;
        __half2* op = (__half2*)(o + (size_t)(base + i) * DIM + head * 32);
        #pragma unroll
        for (int d4 = 0; d4 < 8; d4++) {
            op[d4 * 2]     = __floats2half2_rn(accv[d4].x * inv, accv[d4].y * inv);
            op[d4 * 2 + 1] = __floats2half2_rn(accv[d4].z * inv, accv[d4].w * inv);
        }
    }
}

// ---------------- PatchExpand pixel-shuffle + LN over 192: 1 warp per token ----------
__global__ __launch_bounds__(256)
void expand_ln_kernel(const float* __restrict__ e, float* __restrict__ out,
                      const float* __restrict__ g, const float* __restrict__ b) {
    int tt = blockIdx.x * 8 + (threadIdx.x >> 5);
    int lane = threadIdx.x & 31;
    int bb = tt / 12544;
    int rem = tt % 12544;
    int oh = rem / 112, ow = rem % 112;
    int h = oh >> 1, p = oh & 1, w = ow >> 1, q = ow & 1;
    int erow = bb * 3136 + h * 56 + w;
    const float* sp = e + (size_t)erow * EXPD + (p * 2 + q) * 192;
    float v[6];
    float s = 0.f;
    #pragma unroll
    for (int k = 0; k < 6; k++) { v[k] = sp[lane + k * 32]; s += v[k]; }
    float m = warp_sum(s) * (1.f / 192.f);
    float vs = 0.f;
    #pragma unroll
    for (int k = 0; k < 6; k++) { v[k] -= m; vs += v[k] * v[k]; }
    float inv = rsqrtf(warp_sum(vs) * (1.f / 192.f) + 1e-5f);
    float* dp = out + (size_t)tt * 192;
    #pragma unroll
    for (int k = 0; k < 6; k++) {
        int c = lane + k * 32;
        dp[c] = v[k] * inv * g[c] + b[c];
    }
}

// ---------------- host orchestration ----------------
extern "C" void kernel_launch(void* const* d_in, const int* in_sizes, int n_in,
                              void* d_out, int out_size) {
    const float* x    = (const float*)d_in[0];
    const float* n1g  = (const float*)d_in[1];
    const float* n1b  = (const float*)d_in[2];
    const float* qkvw = (const float*)d_in[3];
    const float* qkvb = (const float*)d_in[4];
    const float* rpb  = (const float*)d_in[5];
    const float* pw   = (const float*)d_in[6];
    const float* pb   = (const float*)d_in[7];
    const float* n2g  = (const float*)d_in[8];
    const float* n2b  = (const float*)d_in[9];
    const float* f1w  = (const float*)d_in[10];
    const float* f1b  = (const float*)d_in[11];
    const float* f2w  = (const float*)d_in[12];
    const float* f2b  = (const float*)d_in[13];
    const float* ew   = (const float*)d_in[14];
    const float* eg   = (const float*)d_in[15];
    const float* ebv  = (const float*)d_in[16];

    float *xb, *bigb;
    __half *xh, *yh, *oh, *wh;
    cudaGetSymbolAddress((void**)&xb,   g_x);
    cudaGetSymbolAddress((void**)&xh,   g_xh);
    cudaGetSymbolAddress((void**)&yh,   g_y);
    cudaGetSymbolAddress((void**)&oh,   g_o);
    cudaGetSymbolAddress((void**)&bigb, g_big);
    cudaGetSymbolAddress((void**)&wh,   g_w);

    static int smem_set = 0;
    const int GEMM_SMEM = 3 * STG * sizeof(__half);   // 107520 B
    if (!smem_set) {
        cudaFuncSetAttribute(gemm_fp16,
                             cudaFuncAttributeMaxDynamicSharedMemorySize, GEMM_SMEM);
        smem_set = 1;
    }

    tohalf_kernel<<<(884736/4 + 255)/256, 256>>>((const float4*)qkvw, wh + W_QKV, 884736/4);
    tohalf_kernel<<<(294912/4 + 255)/256, 256>>>((const float4*)pw,   wh + W_PROJ, 294912/4);
    tohalf_kernel<<<(1179648/4 + 255)/256, 256>>>((const float4*)f1w, wh + W_FC1, 1179648/4);
    tohalf_kernel<<<(1179648/4 + 255)/256, 256>>>((const float4*)f2w, wh + W_FC2, 1179648/4);

    const int MB = TOK / 128;
    for (int i = 0; i < 2; i++) {
        int sh = i;
        const float* res = (i == 0) ? x : xb;
        ln384_kernel<<<TOK / 8, 256>>>(res, yh, n1g + i * DIM, n1b + i * DIM, sh ? 2 : 1);
        gemm_fp16<<<dim3(QKVD / 128, MB), 128, GEMM_SMEM>>>(
            yh, wh + W_QKV + (size_t)i * DIM * QKVD, qkvb + i * QKVD,
            bigb, nullptr, nullptr, DIM, QKVD, 0, 0, 1);
        attn_kernel<<<1024 * 6, 128>>>((const __half*)bigb, oh, rpb + i * 169 * 12, sh);
        gemm_fp16<<<dim3(DIM / 128, MB), 128, GEMM_SMEM>>>(
            oh, wh + W_PROJ + (size_t)i * DIM * DIM, pb + i * DIM,
            xb, nullptr, res, DIM, DIM, 2, sh, 0);
        ln384_kernel<<<TOK / 8, 256>>>(xb, yh, n2g + i * DIM, n2b + i * DIM, 0);
        gemm_fp16<<<dim3(FFN / 128, MB), 128, GEMM_SMEM>>>(
            yh, wh + W_FC1 + (size_t)i * DIM * FFN, f1b + i * FFN,
            bigb, nullptr, nullptr, DIM, FFN, 1, 0, 1);
        gemm_fp16<<<dim3(DIM / 128, MB), 128, GEMM_SMEM>>>(
            (const __half*)bigb, wh + W_FC2 + (size_t)i * FFN * DIM, f2b + i * DIM,
            xb, xh, xb, FFN, DIM, 3, 0, 0);
    }

    tohalf_kernel<<<(294912/4 + 255)/256, 256>>>((const float4*)ew, wh + W_EXP, 294912/4);
    gemm_fp16<<<dim3(EXPD / 128, MB), 128, GEMM_SMEM>>>(
        xh, wh + W_EXP, nullptr, bigb, nullptr, nullptr, DIM, EXPD, 0, 0, 0);
    expand_ln_kernel<<<TOK * 4 / 8, 256>>>(bigb, (float*)d_out, eg, ebv);
}

// round 13
// speedup vs baseline: 1.1382x; 1.0857x over previous
#include <cuda_runtime.h>
#include <cuda_fp16.h>
#include <math.h>
#include <stdint.h>
#include <mma.h>
using namespace nvcuda;

// ---------------- problem constants ----------------
#define TOK   50176
#define DIM   384
#define QKVD  1152
#define FFN   1536
#define EXPD  768

// ---------------- scratch ----------------
static __device__ float  g_x  [TOK * DIM];
static __device__ __half g_xh [TOK * DIM];
static __device__ __half g_y  [TOK * DIM];
static __device__ __half g_o  [TOK * DIM];
static __device__ float  g_big[TOK * FFN];
static __device__ __half g_w  [3833856];

#define W_QKV 0
#define W_PROJ 884736
#define W_FC1 1179648
#define W_FC2 2359296
#define W_EXP 3538944

// ---------------- helpers ----------------
__device__ __forceinline__ uint32_t smem_u32(const void* p) {
    uint32_t a;
    asm("{ .reg .u64 t; cvta.to.shared.u64 t, %1; cvt.u32.u64 %0, t; }" : "=r"(a) : "l"(p));
    return a;
}
__device__ __forceinline__ void cp16(uint32_t s, const void* g) {
    asm volatile("cp.async.cg.shared.global [%0], [%1], 16;" :: "r"(s), "l"(g) : "memory");
}
#define CP_COMMIT() asm volatile("cp.async.commit_group;" ::: "memory")
#define CP_WAIT(n)  asm volatile("cp.async.wait_group %0;" :: "n"(n) : "memory")

__device__ __forceinline__ int map_row(int ridx, int shifted) {
    int n  = ridx % 49;
    int wi = (ridx / 49) & 63;
    int b  = ridx / (49 * 64);
    int r = n / 7, c = n % 7;
    int wh = wi >> 3, ww = wi & 7;
    int h = wh * 7 + r, w = ww * 7 + c;
    if (shifted) { h = (h + 3) % 56; w = (w + 3) % 56; }
    return b * 3136 + h * 56 + w;
}

__device__ __forceinline__ float warp_sum(float v) {
    #pragma unroll
    for (int o = 16; o; o >>= 1) v += __shfl_xor_sync(0xffffffffu, v, o);
    return v;
}
__device__ __forceinline__ float gelu(float v) {
    return 0.5f * v * (1.f + erff(v * 0.7071067811865476f));
}

// ---------------- fp16 wmma GEMM (round-10 config, unchanged) ----------------
#define ASTR 72
#define BSTR 136
#define A_STAGE (128 * ASTR)
#define B_STAGE (64 * BSTR)
#define STG (A_STAGE + B_STAGE)
#define OSTR 132

__global__ __launch_bounds__(128, 2)
void gemm_fp16(const __half* __restrict__ A, const __half* __restrict__ W,
               const float* __restrict__ bias, void* __restrict__ Cv,
               __half* __restrict__ mirror, const float* __restrict__ resid,
               int K, int Nc, int epilogue, int shifted, int out_half) {
    extern __shared__ __align__(16) char smraw[];
    __half* smh = (__half*)smraw;
    float*  smf = (float*)smraw;
    int tid = threadIdx.x;
    int wid = tid >> 5;
    int wm = (wid & 1) * 64;
    int wn = (wid >> 1) * 64;
    int rowBase = blockIdx.y * 128;
    int colBase = blockIdx.x * 128;
    int nk = K >> 6;

    wmma::fragment<wmma::accumulator, 16, 16, 16, float> acc[4][4];
    #pragma unroll
    for (int i = 0; i < 4; i++)
        #pragma unroll
        for (int j = 0; j < 4; j++) wmma::fill_fragment(acc[i][j], 0.f);

    #define STAGE_LOAD(kt, buf) do {                                              \
        __half* As_ = smh + (buf) * STG;                                          \
        __half* Bs_ = As_ + A_STAGE;                                              \
        uint32_t as_ = smem_u32(As_), bs_ = smem_u32(Bs_);                        \
        int kg_ = (kt) * 64;                                                      \
        _Pragma("unroll")                                                         \
        for (int l = 0; l < 8; l++) {                                             \
            int c = tid + l * 128;                                                \
            int r = c >> 3, q = (c & 7) * 8;                                      \
            cp16(as_ + (uint32_t)(r * ASTR + q) * 2,                              \
                 A + (size_t)(rowBase + r) * K + kg_ + q);                        \
            int kr = c >> 4, nq = (c & 15) * 8;                                   \
            cp16(bs_ + (uint32_t)(kr * BSTR + nq) * 2,                            \
                 W + (size_t)(kg_ + kr) * Nc + colBase + nq);                     \
        }                                                                         \
    } while (0)

    STAGE_LOAD(0, 0); CP_COMMIT();
    STAGE_LOAD(1, 1); CP_COMMIT();

    for (int kt = 0; kt < nk; kt++) {
        if (kt + 1 < nk) { CP_WAIT(1); } else { CP_WAIT(0); }
        __syncthreads();
        if (kt + 2 < nk) { STAGE_LOAD(kt + 2, (kt + 2) % 3); CP_COMMIT(); }

        const __half* As = smh + (kt % 3) * STG;
        const __half* Bs = As + A_STAGE;
        #pragma unroll
        for (int k16 = 0; k16 < 4; k16++) {
            wmma::fragment<wmma::matrix_a, 16, 16, 16, __half, wmma::row_major> af[4];
            wmma::fragment<wmma::matrix_b, 16, 16, 16, __half, wmma::row_major> bf[4];
            #pragma unroll
            for (int i = 0; i < 4; i++)
                wmma::load_matrix_sync(af[i], As + (wm + i * 16) * ASTR + k16 * 16, ASTR);
            #pragma unroll
            for (int j = 0; j < 4; j++)
                wmma::load_matrix_sync(bf[j], Bs + (k16 * 16) * BSTR + wn + j * 16, BSTR);
            #pragma unroll
            for (int i = 0; i < 4; i++)
                #pragma unroll
                for (int j = 0; j < 4; j++)
                    wmma::mma_sync(acc[i][j], af[i], bf[j], acc[i][j]);
        }
    }
    __syncthreads();

    #pragma unroll
    for (int i = 0; i < 4; i++)
        #pragma unroll
        for (int j = 0; j < 4; j++)
            wmma::store_matrix_sync(smf + (wm + i * 16) * OSTR + wn + j * 16,
                                    acc[i][j], OSTR, wmma::mem_row_major);
    __syncthreads();

    if (epilogue <= 1) {
        if (out_half) {
            __half* C = (__half*)Cv;
            #pragma unroll 4
            for (int e = 0; e < 32; e++) {
                int idx = tid + e * 128;
                int r = idx >> 5, c4 = (idx & 31) * 4;
                int gc = colBase + c4;
                float4 v = *(const float4*)(smf + r * OSTR + c4);
                if (bias) {
                    float4 bv = *(const float4*)(bias + gc);
                    v.x += bv.x; v.y += bv.y; v.z += bv.z; v.w += bv.w;
                }
                if (epilogue == 1) {
                    v.x = gelu(v.x); v.y = gelu(v.y); v.z = gelu(v.z); v.w = gelu(v.w);
                }
                __half2 h0 = __floats2half2_rn(v.x, v.y);
                __half2 h1 = __floats2half2_rn(v.z, v.w);
                __half2* cp = (__half2*)(C + (size_t)(rowBase + r) * Nc + gc);
                cp[0] = h0; cp[1] = h1;
            }
        } else {
            float* C = (float*)Cv;
            #pragma unroll 4
            for (int e = 0; e < 32; e++) {
                int idx = tid + e * 128;
                int r = idx >> 5, c4 = (idx & 31) * 4;
                int gc = colBase + c4;
                float4 v = *(const float4*)(smf + r * OSTR + c4);
                if (bias) {
                    float4 bv = *(const float4*)(bias + gc);
                    v.x += bv.x; v.y += bv.y; v.z += bv.z; v.w += bv.w;
                }
                *(float4*)(C + (size_t)(rowBase + r) * Nc + gc) = v;
            }
        }
    } else {
        float* C = (float*)Cv;
        #pragma unroll 4
        for (int e = 0; e < 32; e++) {
            int idx = tid + e * 128;
            int r = idx >> 5, c4 = (idx & 31) * 4;
            int gr = rowBase + r, gc = colBase + c4;
            float4 v = *(const float4*)(smf + r * OSTR + c4);
            float4 bv = *(const float4*)(bias + gc);
            v.x += bv.x; v.y += bv.y; v.z += bv.z; v.w += bv.w;
            int orow = (epilogue == 2) ? map_row(gr, shifted) : gr;
            size_t off = (size_t)orow * Nc + gc;
            float4 rv = *(const float4*)(resid + off);
            v.x += rv.x; v.y += rv.y; v.z += rv.z; v.w += rv.w;
            *(float4*)(C + off) = v;
            if (epilogue == 3) {
                __half2* mp = (__half2*)(mirror + off);
                mp[0] = __floats2half2_rn(v.x, v.y);
                mp[1] = __floats2half2_rn(v.z, v.w);
            }
        }
    }
}

// ---------------- weight fp32 -> fp16 ----------------
__global__ void tohalf_kernel(const float4* __restrict__ in, __half* __restrict__ out, int n4) {
    int i = blockIdx.x * blockDim.x + threadIdx.x;
    if (i < n4) {
        float4 v = in[i];
        __half2* o = (__half2*)(out + i * 4);
        o[0] = __floats2half2_rn(v.x, v.y);
        o[1] = __floats2half2_rn(v.z, v.w);
    }
}

// ---------------- LayerNorm over 384: 1 warp per row, float4 I/O ----------------
__global__ __launch_bounds__(256)
void ln384_kernel(const float* __restrict__ src, __half* __restrict__ dst,
                  const float* __restrict__ g, const float* __restrict__ b,
                  int mode) {
    int row = blockIdx.x * 8 + (threadIdx.x >> 5);
    int lane = threadIdx.x & 31;
    int t = (mode == 0) ? row : map_row(row, mode == 2);
    const float4* sp = (const float4*)(src + (size_t)t * DIM);
    float4 v[3];
    float s = 0.f;
    #pragma unroll
    for (int e = 0; e < 3; e++) {
        v[e] = sp[lane + e * 32];
        s += v[e].x + v[e].y + v[e].z + v[e].w;
    }
    float m = warp_sum(s) * (1.f / 384.f);
    float vs = 0.f;
    #pragma unroll
    for (int e = 0; e < 3; e++) {
        v[e].x -= m; v[e].y -= m; v[e].z -= m; v[e].w -= m;
        vs += v[e].x * v[e].x + v[e].y * v[e].y + v[e].z * v[e].z + v[e].w * v[e].w;
    }
    float inv = rsqrtf(warp_sum(vs) * (1.f / 384.f) + 1e-5f);
    __half* dp = dst + (size_t)row * DIM;
    #pragma unroll
    for (int e = 0; e < 3; e++) {
        int c4 = (lane + e * 32) * 4;
        float4 gv = *(const float4*)(g + c4);
        float4 bv = *(const float4*)(b + c4);
        float o0 = v[e].x * inv * gv.x + bv.x;
        float o1 = v[e].y * inv * gv.y + bv.y;
        float o2 = v[e].z * inv * gv.z + bv.z;
        float o3 = v[e].w * inv * gv.w + bv.w;
        __half2* hp = (__half2*)(dp + c4);
        hp[0] = __floats2half2_rn(o0, o1);
        hp[1] = __floats2half2_rn(o2, o3);
    }
}

// ---------------- HMMA windowed attention v2: 1 block per (window, head) ----
// QK^T and PV on tensor cores; softmax with smem bias + precomputed labels + __expf.
__global__ __launch_bounds__(128)
void attn_mma_kernel(const __half* __restrict__ qkv, __half* __restrict__ o,
                     const float* __restrict__ rpb, int shifted) {
    __shared__ __half qs[64 * 40];
    __shared__ __half ks[64 * 40];
    __shared__ __half vsm[64 * 40];
    __shared__ float  ss[64 * 68];     // scores; reused (ld 36) for PV output
    __shared__ __half ps[64 * 72];
    __shared__ float  rsum[64];
    __shared__ float  bias_s[169];
    __shared__ int    lab_s[49];

    int head = blockIdx.x % 12;
    int win  = blockIdx.x / 12;
    int wi = win & 63;
    int wh = wi >> 3, ww = wi & 7;
    int base = win * 49;
    int tid = threadIdx.x;
    int wid = tid >> 5;

    const float sc = 0.17677669529663687f;
    const __half2 z2 = __float2half2_rn(0.f);

    // stage bias table + mask labels
    for (int idx = tid; idx < 169; idx += 128)
        bias_s[idx] = rpb[idx * 12 + head];
    if (tid < 49) {
        int rj = tid / 7, cj = tid % 7;
        int hh = wh * 7 + rj, wc = ww * 7 + cj;
        int gh = hh < 49 ? 0 : (hh < 53 ? 1 : 2);
        int gw = wc < 49 ? 0 : (wc < 53 ? 1 : 2);
        lab_s[tid] = gh * 3 + gw;
    }

    // load q (scaled), k, v; zero pads
    for (int idx = tid; idx < 64 * 16; idx += 128) {
        int j = idx >> 4, d2 = (idx & 15) * 2;
        int off = j * 40 + d2;
        if (j < 49) {
            size_t ro = (size_t)(base + j) * QKVD + head * 32 + d2;
            __half2 qv = *(const __half2*)(qkv + ro);
            float2 qf = __half22float2(qv);
            *(__half2*)(qs + off)  = __floats2half2_rn(qf.x * sc, qf.y * sc);
            *(__half2*)(ks + off)  = *(const __half2*)(qkv + ro + 384);
            *(__half2*)(vsm + off) = *(const __half2*)(qkv + ro + 768);
        } else {
            *(__half2*)(qs + off)  = z2;
            *(__half2*)(ks + off)  = z2;
            *(__half2*)(vsm + off) = z2;
        }
    }
    for (int idx = tid; idx < 64 * 4; idx += 128) {
        int j = idx >> 2, d2 = 32 + (idx & 3) * 2;
        int off = j * 40 + d2;
        *(__half2*)(qs + off)  = z2;
        *(__half2*)(ks + off)  = z2;
        *(__half2*)(vsm + off) = z2;
    }
    __syncthreads();

    // QK^T: warp wid -> rows [16w,16w+16) x 64 cols
    {
        wmma::fragment<wmma::accumulator, 16, 16, 16, float> sacc[4];
        #pragma unroll
        for (int n = 0; n < 4; n++) wmma::fill_fragment(sacc[n], 0.f);
        #pragma unroll
        for (int k16 = 0; k16 < 2; k16++) {
            wmma::fragment<wmma::matrix_a, 16, 16, 16, __half, wmma::row_major> aq;
            wmma::load_matrix_sync(aq, qs + (wid * 16) * 40 + k16 * 16, 40);
            #pragma unroll
            for (int n = 0; n < 4; n++) {
                wmma::fragment<wmma::matrix_b, 16, 16, 16, __half, wmma::col_major> bk;
                wmma::load_matrix_sync(bk, ks + (n * 16) * 40 + k16 * 16, 40);
                wmma::mma_sync(sacc[n], aq, bk, sacc[n]);
            }
        }
        #pragma unroll
        for (int n = 0; n < 4; n++)
            wmma::store_matrix_sync(ss + (wid * 16) * 68 + n * 16, sacc[n], 68,
                                    wmma::mem_row_major);
    }
    __syncthreads();

    // softmax: thread t<64 handles row t (smem-only inner loop)
    if (tid < 64) {
        int i = tid;
        if (i < 49) {
            int ri = i / 7, ci = i % 7;
            int lab_i = lab_s[i];
            float sum = 0.f;
            for (int rj = 0; rj < 7; rj++) {
                int rbase = (ri - rj + 6) * 13 + ci + 6;
                #pragma unroll
                for (int cj = 0; cj < 7; cj++) {
                    int j = rj * 7 + cj;
                    float s = ss[i * 68 + j] + bias_s[rbase - cj];
                    if (shifted && lab_s[j] != lab_i) s -= 100.0f;
                    __half eh = __float2half(__expf(s));
                    ps[i * 72 + j] = eh;
                    sum += __half2float(eh);
                }
            }
            #pragma unroll
            for (int j = 49; j < 64; j++) ps[i * 72 + j] = __float2half(0.f);
            rsum[i] = 1.0f / sum;
        } else {
            for (int j = 0; j < 64; j++) ps[i * 72 + j] = __float2half(0.f);
            rsum[i] = 0.f;
        }
    }
    __syncthreads();

    // PV: warp wid -> rows [16w,16w+16) x 32 cols; reuse ss (ld 36)
    {
        wmma::fragment<wmma::accumulator, 16, 16, 16, float> oacc[2];
        #pragma unroll
        for (int n = 0; n < 2; n++) wmma::fill_fragment(oacc[n], 0.f);
        #pragma unroll
        for (int k16 = 0; k16 < 4; k16++) {
            wmma::fragment<wmma::matrix_a, 16, 16, 16, __half, wmma::row_major> ap;
            wmma::load_matrix_sync(ap, ps + (wid * 16) * 72 + k16 * 16, 72);
            #pragma unroll
            for (int n = 0; n < 2; n++) {
                wmma::fragment<wmma::matrix_b, 16, 16, 16, __half, wmma::row_major> bv;
                wmma::load_matrix_sync(bv, vsm + (k16 * 16) * 40 + n * 16, 40);
                wmma::mma_sync(oacc[n], ap, bv, oacc[n]);
            }
        }
        #pragma unroll
        for (int n = 0; n < 2; n++)
            wmma::store_matrix_sync(ss + (wid * 16) * 36 + n * 16, oacc[n], 36,
                                    wmma::mem_row_major);
    }
    __syncthreads();

    // epilogue: rows < 49, 32 cols
    for (int idx = tid; idx < 49 * 16; idx += 128) {
        int i = idx >> 4, d2 = (idx & 15) * 2;
        float inv = rsum[i];
        float v0 = ss[i * 36 + d2]     * inv;
        float v1 = ss[i * 36 + d2 + 1] * inv;
        *(__half2*)(o + (size_t)(base + i) * DIM + head * 32 + d2) =
            __floats2half2_rn(v0, v1);
    }
}

// ---------------- PatchExpand pixel-shuffle + LN over 192: 1 warp per token ----------
__global__ __launch_bounds__(256)
void expand_ln_kernel(const float* __restrict__ e, float* __restrict__ out,
                      const float* __restrict__ g, const float* __restrict__ b) {
    int tt = blockIdx.x * 8 + (threadIdx.x >> 5);
    int lane = threadIdx.x & 31;
    int bb = tt / 12544;
    int rem = tt % 12544;
    int oh = rem / 112, ow = rem % 112;
    int h = oh >> 1, p = oh & 1, w = ow >> 1, q = ow & 1;
    int erow = bb * 3136 + h * 56 + w;
    const float* sp = e + (size_t)erow * EXPD + (p * 2 + q) * 192;
    float v[6];
    float s = 0.f;
    #pragma unroll
    for (int k = 0; k < 6; k++) { v[k] = sp[lane + k * 32]; s += v[k]; }
    float m = warp_sum(s) * (1.f / 192.f);
    float vs = 0.f;
    #pragma unroll
    for (int k = 0; k < 6; k++) { v[k] -= m; vs += v[k] * v[k]; }
    float inv = rsqrtf(warp_sum(vs) * (1.f / 192.f) + 1e-5f);
    float* dp = out + (size_t)tt * 192;
    #pragma unroll
    for (int k = 0; k < 6; k++) {
        int c = lane + k * 32;
        dp[c] = v[k] * inv * g[c] + b[c];
    }
}

// ---------------- host orchestration ----------------
extern "C" void kernel_launch(void* const* d_in, const int* in_sizes, int n_in,
                              void* d_out, int out_size) {
    const float* x    = (const float*)d_in[0];
    const float* n1g  = (const float*)d_in[1];
    const float* n1b  = (const float*)d_in[2];
    const float* qkvw = (const float*)d_in[3];
    const float* qkvb = (const float*)d_in[4];
    const float* rpb  = (const float*)d_in[5];
    const float* pw   = (const float*)d_in[6];
    const float* pb   = (const float*)d_in[7];
    const float* n2g  = (const float*)d_in[8];
    const float* n2b  = (const float*)d_in[9];
    const float* f1w  = (const float*)d_in[10];
    const float* f1b  = (const float*)d_in[11];
    const float* f2w  = (const float*)d_in[12];
    const float* f2b  = (const float*)d_in[13];
    const float* ew   = (const float*)d_in[14];
    const float* eg   = (const float*)d_in[15];
    const float* ebv  = (const float*)d_in[16];

    float *xb, *bigb;
    __half *xh, *yh, *oh, *wh;
    cudaGetSymbolAddress((void**)&xb,   g_x);
    cudaGetSymbolAddress((void**)&xh,   g_xh);
    cudaGetSymbolAddress((void**)&yh,   g_y);
    cudaGetSymbolAddress((void**)&oh,   g_o);
    cudaGetSymbolAddress((void**)&bigb, g_big);
    cudaGetSymbolAddress((void**)&wh,   g_w);

    static int smem_set = 0;
    const int GEMM_SMEM = 3 * STG * sizeof(__half);   // 107520 B
    if (!smem_set) {
        cudaFuncSetAttribute(gemm_fp16,
                             cudaFuncAttributeMaxDynamicSharedMemorySize, GEMM_SMEM);
        smem_set = 1;
    }

    tohalf_kernel<<<(884736/4 + 255)/256, 256>>>((const float4*)qkvw, wh + W_QKV, 884736/4);
    tohalf_kernel<<<(294912/4 + 255)/256, 256>>>((const float4*)pw,   wh + W_PROJ, 294912/4);
    tohalf_kernel<<<(1179648/4 + 255)/256, 256>>>((const float4*)f1w, wh + W_FC1, 1179648/4);
    tohalf_kernel<<<(1179648/4 + 255)/256, 256>>>((const float4*)f2w, wh + W_FC2, 1179648/4);

    const int MB = TOK / 128;
    for (int i = 0; i < 2; i++) {
        int sh = i;
        const float* res = (i == 0) ? x : xb;
        ln384_kernel<<<TOK / 8, 256>>>(res, yh, n1g + i * DIM, n1b + i * DIM, sh ? 2 : 1);
        gemm_fp16<<<dim3(QKVD / 128, MB), 128, GEMM_SMEM>>>(
            yh, wh + W_QKV + (size_t)i * DIM * QKVD, qkvb + i * QKVD,
            bigb, nullptr, nullptr, DIM, QKVD, 0, 0, 1);
        attn_mma_kernel<<<1024 * 12, 128>>>((const __half*)bigb, oh, rpb + i * 169 * 12, sh);
        gemm_fp16<<<dim3(DIM / 128, MB), 128, GEMM_SMEM>>>(
            oh, wh + W_PROJ + (size_t)i * DIM * DIM, pb + i * DIM,
            xb, nullptr, res, DIM, DIM, 2, sh, 0);
        ln384_kernel<<<TOK / 8, 256>>>(xb, yh, n2g + i * DIM, n2b + i * DIM, 0);
        gemm_fp16<<<dim3(FFN / 128, MB), 128, GEMM_SMEM>>>(
            yh, wh + W_FC1 + (size_t)i * DIM * FFN, f1b + i * FFN,
            bigb, nullptr, nullptr, DIM, FFN, 1, 0, 1);
        gemm_fp16<<<dim3(DIM / 128, MB), 128, GEMM_SMEM>>>(
            (const __half*)bigb, wh + W_FC2 + (size_t)i * FFN * DIM, f2b + i * DIM,
            xb, xh, xb, FFN, DIM, 3, 0, 0);
    }

    tohalf_kernel<<<(294912/4 + 255)/256, 256>>>((const float4*)ew, wh + W_EXP, 294912/4);
    gemm_fp16<<<dim3(EXPD / 128, MB), 128, GEMM_SMEM>>>(
        xh, wh + W_EXP, nullptr, bigb, nullptr, nullptr, DIM, EXPD, 0, 0, 0);
    expand_ln_kernel<<<TOK * 4 / 8, 256>>>(bigb, (float*)d_out, eg, ebv);
}

// round 14
// speedup vs baseline: 1.1561x; 1.0158x over previous
#include <cuda_runtime.h>
#include <cuda_fp16.h>
#include <math.h>
#include <stdint.h>
#include <mma.h>
using namespace nvcuda;

// ---------------- problem constants ----------------
#define TOK   50176
#define DIM   384
#define QKVD  1152
#define FFN   1536
#define EXPD  768

// ---------------- scratch ----------------
static __device__ float  g_x  [TOK * DIM];
static __device__ __half g_xh [TOK * DIM];
static __device__ __half g_y  [TOK * DIM];
static __device__ __half g_o  [TOK * DIM];
static __device__ float  g_big[TOK * FFN];
static __device__ __half g_w  [3833856];

#define W_QKV 0
#define W_PROJ 884736
#define W_FC1 1179648
#define W_FC2 2359296
#define W_EXP 3538944

// ---------------- helpers ----------------
__device__ __forceinline__ uint32_t smem_u32(const void* p) {
    uint32_t a;
    asm("{ .reg .u64 t; cvta.to.shared.u64 t, %1; cvt.u32.u64 %0, t; }" : "=r"(a) : "l"(p));
    return a;
}
__device__ __forceinline__ void cp16(uint32_t s, const void* g) {
    asm volatile("cp.async.cg.shared.global [%0], [%1], 16;" :: "r"(s), "l"(g) : "memory");
}
#define CP_COMMIT() asm volatile("cp.async.commit_group;" ::: "memory")
#define CP_WAIT(n)  asm volatile("cp.async.wait_group %0;" :: "n"(n) : "memory")

__device__ __forceinline__ int map_row(int ridx, int shifted) {
    int n  = ridx % 49;
    int wi = (ridx / 49) & 63;
    int b  = ridx / (49 * 64);
    int r = n / 7, c = n % 7;
    int wh = wi >> 3, ww = wi & 7;
    int h = wh * 7 + r, w = ww * 7 + c;
    if (shifted) { h = (h + 3) % 56; w = (w + 3) % 56; }
    return b * 3136 + h * 56 + w;
}

__device__ __forceinline__ float warp_sum(float v) {
    #pragma unroll
    for (int o = 16; o; o >>= 1) v += __shfl_xor_sync(0xffffffffu, v, o);
    return v;
}
__device__ __forceinline__ float gelu(float v) {
    return 0.5f * v * (1.f + erff(v * 0.7071067811865476f));
}

// ---------------- fp16 wmma GEMM (round-10 config, unchanged) ----------------
#define ASTR 72
#define BSTR 136
#define A_STAGE (128 * ASTR)
#define B_STAGE (64 * BSTR)
#define STG (A_STAGE + B_STAGE)
#define OSTR 132

__global__ __launch_bounds__(128, 2)
void gemm_fp16(const __half* __restrict__ A, const __half* __restrict__ W,
               const float* __restrict__ bias, void* __restrict__ Cv,
               __half* __restrict__ mirror, const float* __restrict__ resid,
               int K, int Nc, int epilogue, int shifted, int out_half) {
    extern __shared__ __align__(16) char smraw[];
    __half* smh = (__half*)smraw;
    float*  smf = (float*)smraw;
    int tid = threadIdx.x;
    int wid = tid >> 5;
    int wm = (wid & 1) * 64;
    int wn = (wid >> 1) * 64;
    int rowBase = blockIdx.y * 128;
    int colBase = blockIdx.x * 128;
    int nk = K >> 6;

    wmma::fragment<wmma::accumulator, 16, 16, 16, float> acc[4][4];
    #pragma unroll
    for (int i = 0; i < 4; i++)
        #pragma unroll
        for (int j = 0; j < 4; j++) wmma::fill_fragment(acc[i][j], 0.f);

    #define STAGE_LOAD(kt, buf) do {                                              \
        __half* As_ = smh + (buf) * STG;                                          \
        __half* Bs_ = As_ + A_STAGE;                                              \
        uint32_t as_ = smem_u32(As_), bs_ = smem_u32(Bs_);                        \
        int kg_ = (kt) * 64;                                                      \
        _Pragma("unroll")                                                         \
        for (int l = 0; l < 8; l++) {                                             \
            int c = tid + l * 128;                                                \
            int r = c >> 3, q = (c & 7) * 8;                                      \
            cp16(as_ + (uint32_t)(r * ASTR + q) * 2,                              \
                 A + (size_t)(rowBase + r) * K + kg_ + q);                        \
            int kr = c >> 4, nq = (c & 15) * 8;                                   \
            cp16(bs_ + (uint32_t)(kr * BSTR + nq) * 2,                            \
                 W + (size_t)(kg_ + kr) * Nc + colBase + nq);                     \
        }                                                                         \
    } while (0)

    STAGE_LOAD(0, 0); CP_COMMIT();
    STAGE_LOAD(1, 1); CP_COMMIT();

    for (int kt = 0; kt < nk; kt++) {
        if (kt + 1 < nk) { CP_WAIT(1); } else { CP_WAIT(0); }
        __syncthreads();
        if (kt + 2 < nk) { STAGE_LOAD(kt + 2, (kt + 2) % 3); CP_COMMIT(); }

        const __half* As = smh + (kt % 3) * STG;
        const __half* Bs = As + A_STAGE;
        #pragma unroll
        for (int k16 = 0; k16 < 4; k16++) {
            wmma::fragment<wmma::matrix_a, 16, 16, 16, __half, wmma::row_major> af[4];
            wmma::fragment<wmma::matrix_b, 16, 16, 16, __half, wmma::row_major> bf[4];
            #pragma unroll
            for (int i = 0; i < 4; i++)
                wmma::load_matrix_sync(af[i], As + (wm + i * 16) * ASTR + k16 * 16, ASTR);
            #pragma unroll
            for (int j = 0; j < 4; j++)
                wmma::load_matrix_sync(bf[j], Bs + (k16 * 16) * BSTR + wn + j * 16, BSTR);
            #pragma unroll
            for (int i = 0; i < 4; i++)
                #pragma unroll
                for (int j = 0; j < 4; j++)
                    wmma::mma_sync(acc[i][j], af[i], bf[j], acc[i][j]);
        }
    }
    __syncthreads();

    #pragma unroll
    for (int i = 0; i < 4; i++)
        #pragma unroll
        for (int j = 0; j < 4; j++)
            wmma::store_matrix_sync(smf + (wm + i * 16) * OSTR + wn + j * 16,
                                    acc[i][j], OSTR, wmma::mem_row_major);
    __syncthreads();

    if (epilogue <= 1) {
        if (out_half) {
            __half* C = (__half*)Cv;
            #pragma unroll 4
            for (int e = 0; e < 32; e++) {
                int idx = tid + e * 128;
                int r = idx >> 5, c4 = (idx & 31) * 4;
                int gc = colBase + c4;
                float4 v = *(const float4*)(smf + r * OSTR + c4);
                if (bias) {
                    float4 bv = *(const float4*)(bias + gc);
                    v.x += bv.x; v.y += bv.y; v.z += bv.z; v.w += bv.w;
                }
                if (epilogue == 1) {
                    v.x = gelu(v.x); v.y = gelu(v.y); v.z = gelu(v.z); v.w = gelu(v.w);
                }
                __half2 h0 = __floats2half2_rn(v.x, v.y);
                __half2 h1 = __floats2half2_rn(v.z, v.w);
                __half2* cp = (__half2*)(C + (size_t)(rowBase + r) * Nc + gc);
                cp[0] = h0; cp[1] = h1;
            }
        } else {
            float* C = (float*)Cv;
            #pragma unroll 4
            for (int e = 0; e < 32; e++) {
                int idx = tid + e * 128;
                int r = idx >> 5, c4 = (idx & 31) * 4;
                int gc = colBase + c4;
                float4 v = *(const float4*)(smf + r * OSTR + c4);
                if (bias) {
                    float4 bv = *(const float4*)(bias + gc);
                    v.x += bv.x; v.y += bv.y; v.z += bv.z; v.w += bv.w;
                }
                *(float4*)(C + (size_t)(rowBase + r) * Nc + gc) = v;
            }
        }
    } else {
        float* C = (float*)Cv;
        #pragma unroll 4
        for (int e = 0; e < 32; e++) {
            int idx = tid + e * 128;
            int r = idx >> 5, c4 = (idx & 31) * 4;
            int gr = rowBase + r, gc = colBase + c4;
            float4 v = *(const float4*)(smf + r * OSTR + c4);
            float4 bv = *(const float4*)(bias + gc);
            v.x += bv.x; v.y += bv.y; v.z += bv.z; v.w += bv.w;
            int orow = (epilogue == 2) ? map_row(gr, shifted) : gr;
            size_t off = (size_t)orow * Nc + gc;
            float4 rv = *(const float4*)(resid + off);
            v.x += rv.x; v.y += rv.y; v.z += rv.z; v.w += rv.w;
            *(float4*)(C + off) = v;
            if (epilogue == 3) {
                __half2* mp = (__half2*)(mirror + off);
                mp[0] = __floats2half2_rn(v.x, v.y);
                mp[1] = __floats2half2_rn(v.z, v.w);
            }
        }
    }
}

// ---------------- fused weight fp32 -> fp16 (all 5 tensors, one launch) ----------
#define N4_QKV  221184
#define N4_PROJ 73728
#define N4_FC1  294912
#define N4_FC2  294912
#define N4_EXP  73728
#define N4_ALL  (N4_QKV + N4_PROJ + N4_FC1 + N4_FC2 + N4_EXP)   // 958464

__global__ void tohalf_all(const float4* __restrict__ a0, const float4* __restrict__ a1,
                           const float4* __restrict__ a2, const float4* __restrict__ a3,
                           const float4* __restrict__ a4, __half* __restrict__ out) {
    int i = blockIdx.x * blockDim.x + threadIdx.x;
    if (i >= N4_ALL) return;
    const float4* src; int local; int off;
    if (i < N4_QKV) { src = a0; local = i; off = W_QKV; }
    else if (i < N4_QKV + N4_PROJ) { src = a1; local = i - N4_QKV; off = W_PROJ; }
    else if (i < N4_QKV + N4_PROJ + N4_FC1) { src = a2; local = i - N4_QKV - N4_PROJ; off = W_FC1; }
    else if (i < N4_QKV + N4_PROJ + N4_FC1 + N4_FC2) {
        src = a3; local = i - N4_QKV - N4_PROJ - N4_FC1; off = W_FC2;
    } else { src = a4; local = i - N4_QKV - N4_PROJ - N4_FC1 - N4_FC2; off = W_EXP; }
    float4 v = src[local];
    __half2* o = (__half2*)(out + off + local * 4);
    o[0] = __floats2half2_rn(v.x, v.y);
    o[1] = __floats2half2_rn(v.z, v.w);
}

// ---------------- LayerNorm over 384: 1 warp per row, float4 I/O ----------------
__global__ __launch_bounds__(256)
void ln384_kernel(const float* __restrict__ src, __half* __restrict__ dst,
                  const float* __restrict__ g, const float* __restrict__ b,
                  int mode) {
    int row = blockIdx.x * 8 + (threadIdx.x >> 5);
    int lane = threadIdx.x & 31;
    int t = (mode == 0) ? row : map_row(row, mode == 2);
    const float4* sp = (const float4*)(src + (size_t)t * DIM);
    float4 v[3];
    float s = 0.f;
    #pragma unroll
    for (int e = 0; e < 3; e++) {
        v[e] = sp[lane + e * 32];
        s += v[e].x + v[e].y + v[e].z + v[e].w;
    }
    float m = warp_sum(s) * (1.f / 384.f);
    float vs = 0.f;
    #pragma unroll
    for (int e = 0; e < 3; e++) {
        v[e].x -= m; v[e].y -= m; v[e].z -= m; v[e].w -= m;
        vs += v[e].x * v[e].x + v[e].y * v[e].y + v[e].z * v[e].z + v[e].w * v[e].w;
    }
    float inv = rsqrtf(warp_sum(vs) * (1.f / 384.f) + 1e-5f);
    __half* dp = dst + (size_t)row * DIM;
    #pragma unroll
    for (int e = 0; e < 3; e++) {
        int c4 = (lane + e * 32) * 4;
        float4 gv = *(const float4*)(g + c4);
        float4 bv = *(const float4*)(b + c4);
        float o0 = v[e].x * inv * gv.x + bv.x;
        float o1 = v[e].y * inv * gv.y + bv.y;
        float o2 = v[e].z * inv * gv.z + bv.z;
        float o3 = v[e].w * inv * gv.w + bv.w;
        __half2* hp = (__half2*)(dp + c4);
        hp[0] = __floats2half2_rn(o0, o1);
        hp[1] = __floats2half2_rn(o2, o3);
    }
}

// ---------------- HMMA windowed attention v3: parallel softmax ----------------
__global__ __launch_bounds__(128)
void attn_mma_kernel(const __half* __restrict__ qkv, __half* __restrict__ o,
                     const float* __restrict__ rpb, int shifted) {
    __shared__ __half qs[64 * 40];
    __shared__ __half ks[64 * 40];
    __shared__ __half vsm[64 * 40];
    __shared__ float  ss[64 * 68];     // scores; reused (ld 36) for PV output
    __shared__ __half ps[64 * 72];
    __shared__ float  rsum[64];
    __shared__ float  psum[2][64];
    __shared__ float  bias_s[169];
    __shared__ int    lab_s[49];

    int head = blockIdx.x % 12;
    int win  = blockIdx.x / 12;
    int wi = win & 63;
    int wh = wi >> 3, ww = wi & 7;
    int base = win * 49;
    int tid = threadIdx.x;
    int wid = tid >> 5;

    const float sc = 0.17677669529663687f;
    const __half2 z2 = __float2half2_rn(0.f);

    for (int idx = tid; idx < 169; idx += 128)
        bias_s[idx] = rpb[idx * 12 + head];
    if (tid < 49) {
        int rj = (tid * 37) >> 8, cj = tid - rj * 7;
        int hh = wh * 7 + rj, wc = ww * 7 + cj;
        int gh = hh < 49 ? 0 : (hh < 53 ? 1 : 2);
        int gw = wc < 49 ? 0 : (wc < 53 ? 1 : 2);
        lab_s[tid] = gh * 3 + gw;
    }

    for (int idx = tid; idx < 64 * 16; idx += 128) {
        int j = idx >> 4, d2 = (idx & 15) * 2;
        int off = j * 40 + d2;
        if (j < 49) {
            size_t ro = (size_t)(base + j) * QKVD + head * 32 + d2;
            __half2 qv = *(const __half2*)(qkv + ro);
            float2 qf = __half22float2(qv);
            *(__half2*)(qs + off)  = __floats2half2_rn(qf.x * sc, qf.y * sc);
            *(__half2*)(ks + off)  = *(const __half2*)(qkv + ro + 384);
            *(__half2*)(vsm + off) = *(const __half2*)(qkv + ro + 768);
        } else {
            *(__half2*)(qs + off)  = z2;
            *(__half2*)(ks + off)  = z2;
            *(__half2*)(vsm + off) = z2;
        }
    }
    for (int idx = tid; idx < 64 * 4; idx += 128) {
        int j = idx >> 2, d2 = 32 + (idx & 3) * 2;
        int off = j * 40 + d2;
        *(__half2*)(qs + off)  = z2;
        *(__half2*)(ks + off)  = z2;
        *(__half2*)(vsm + off) = z2;
    }
    __syncthreads();

    // QK^T
    {
        wmma::fragment<wmma::accumulator, 16, 16, 16, float> sacc[4];
        #pragma unroll
        for (int n = 0; n < 4; n++) wmma::fill_fragment(sacc[n], 0.f);
        #pragma unroll
        for (int k16 = 0; k16 < 2; k16++) {
            wmma::fragment<wmma::matrix_a, 16, 16, 16, __half, wmma::row_major> aq;
            wmma::load_matrix_sync(aq, qs + (wid * 16) * 40 + k16 * 16, 40);
            #pragma unroll
            for (int n = 0; n < 4; n++) {
                wmma::fragment<wmma::matrix_b, 16, 16, 16, __half, wmma::col_major> bk;
                wmma::load_matrix_sync(bk, ks + (n * 16) * 40 + k16 * 16, 40);
                wmma::mma_sync(sacc[n], aq, bk, sacc[n]);
            }
        }
        #pragma unroll
        for (int n = 0; n < 4; n++)
            wmma::store_matrix_sync(ss + (wid * 16) * 68 + n * 16, sacc[n], 68,
                                    wmma::mem_row_major);
    }
    __syncthreads();

    // softmax: 2 threads per row (j ranges [0,25) / [25,49))
    {
        int i = tid & 63;
        int hf = tid >> 6;
        if (i < 49) {
            int ri = (i * 37) >> 8, ci = i - ri * 7;
            int lab_i = lab_s[i];
            float sum = 0.f;
            int j0 = hf ? 25 : 0, j1 = hf ? 49 : 25;
            for (int j = j0; j < j1; j++) {
                int rj = (j * 37) >> 8, cj = j - rj * 7;
                float s = ss[i * 68 + j] + bias_s[(ri - rj + 6) * 13 + (ci - cj + 6)];
                if (shifted && lab_s[j] != lab_i) s -= 100.0f;
                __half eh = __float2half(__expf(s));
                ps[i * 72 + j] = eh;
                sum += __half2float(eh);
            }
            psum[hf][i] = sum;
            if (hf) {
                #pragma unroll
                for (int j = 49; j < 64; j++) ps[i * 72 + j] = __float2half(0.f);
            }
        } else {
            int j0 = hf ? 32 : 0, j1 = hf ? 64 : 32;
            for (int j = j0; j < j1; j++) ps[i * 72 + j] = __float2half(0.f);
        }
    }
    __syncthreads();
    if (tid < 64)
        rsum[tid] = (tid < 49) ? 1.0f / (psum[0][tid] + psum[1][tid]) : 0.f;
    __syncthreads();

    // PV
    {
        wmma::fragment<wmma::accumulator, 16, 16, 16, float> oacc[2];
        #pragma unroll
        for (int n = 0; n < 2; n++) wmma::fill_fragment(oacc[n], 0.f);
        #pragma unroll
        for (int k16 = 0; k16 < 4; k16++) {
            wmma::fragment<wmma::matrix_a, 16, 16, 16, __half, wmma::row_major> ap;
            wmma::load_matrix_sync(ap, ps + (wid * 16) * 72 + k16 * 16, 72);
            #pragma unroll
            for (int n = 0; n < 2; n++) {
                wmma::fragment<wmma::matrix_b, 16, 16, 16, __half, wmma::row_major> bv;
                wmma::load_matrix_sync(bv, vsm + (k16 * 16) * 40 + n * 16, 40);
                wmma::mma_sync(oacc[n], ap, bv, oacc[n]);
            }
        }
        #pragma unroll
        for (int n = 0; n < 2; n++)
            wmma::store_matrix_sync(ss + (wid * 16) * 36 + n * 16, oacc[n], 36,
                                    wmma::mem_row_major);
    }
    __syncthreads();

    for (int idx = tid; idx < 49 * 16; idx += 128) {
        int i = idx >> 4, d2 = (idx & 15) * 2;
        float inv = rsum[i];
        float v0 = ss[i * 36 + d2]     * inv;
        float v1 = ss[i * 36 + d2 + 1] * inv;
        *(__half2*)(o + (size_t)(base + i) * DIM + head * 32 + d2) =
            __floats2half2_rn(v0, v1);
    }
}

// ---------------- PatchExpand pixel-shuffle + LN over 192: 1 warp per token ----------
__global__ __launch_bounds__(256)
void expand_ln_kernel(const float* __restrict__ e, float* __restrict__ out,
                      const float* __restrict__ g, const float* __restrict__ b) {
    int tt = blockIdx.x * 8 + (threadIdx.x >> 5);
    int lane = threadIdx.x & 31;
    int bb = tt / 12544;
    int rem = tt % 12544;
    int oh = rem / 112, ow = rem % 112;
    int h = oh >> 1, p = oh & 1, w = ow >> 1, q = ow & 1;
    int erow = bb * 3136 + h * 56 + w;
    const float* sp = e + (size_t)erow * EXPD + (p * 2 + q) * 192;
    float v[6];
    float s = 0.f;
    #pragma unroll
    for (int k = 0; k < 6; k++) { v[k] = sp[lane + k * 32]; s += v[k]; }
    float m = warp_sum(s) * (1.f / 192.f);
    float vs = 0.f;
    #pragma unroll
    for (int k = 0; k < 6; k++) { v[k] -= m; vs += v[k] * v[k]; }
    float inv = rsqrtf(warp_sum(vs) * (1.f / 192.f) + 1e-5f);
    float* dp = out + (size_t)tt * 192;
    #pragma unroll
    for (int k = 0; k < 6; k++) {
        int c = lane + k * 32;
        dp[c] = v[k] * inv * g[c] + b[c];
    }
}

// ---------------- host orchestration ----------------
extern "C" void kernel_launch(void* const* d_in, const int* in_sizes, int n_in,
                              void* d_out, int out_size) {
    const float* x    = (const float*)d_in[0];
    const float* n1g  = (const float*)d_in[1];
    const float* n1b  = (const float*)d_in[2];
    const float* qkvw = (const float*)d_in[3];
    const float* qkvb = (const float*)d_in[4];
    const float* rpb  = (const float*)d_in[5];
    const float* pw   = (const float*)d_in[6];
    const float* pb   = (const float*)d_in[7];
    const float* n2g  = (const float*)d_in[8];
    const float* n2b  = (const float*)d_in[9];
    const float* f1w  = (const float*)d_in[10];
    const float* f1b  = (const float*)d_in[11];
    const float* f2w  = (const float*)d_in[12];
    const float* f2b  = (const float*)d_in[13];
    const float* ew   = (const float*)d_in[14];
    const float* eg   = (const float*)d_in[15];
    const float* ebv  = (const float*)d_in[16];

    float *xb, *bigb;
    __half *xh, *yh, *oh, *wh;
    cudaGetSymbolAddress((void**)&xb,   g_x);
    cudaGetSymbolAddress((void**)&xh,   g_xh);
    cudaGetSymbolAddress((void**)&yh,   g_y);
    cudaGetSymbolAddress((void**)&oh,   g_o);
    cudaGetSymbolAddress((void**)&bigb, g_big);
    cudaGetSymbolAddress((void**)&wh,   g_w);

    static int smem_set = 0;
    const int GEMM_SMEM = 3 * STG * sizeof(__half);   // 107520 B
    if (!smem_set) {
        cudaFuncSetAttribute(gemm_fp16,
                             cudaFuncAttributeMaxDynamicSharedMemorySize, GEMM_SMEM);
        smem_set = 1;
    }

    tohalf_all<<<(N4_ALL + 255) / 256, 256>>>(
        (const float4*)qkvw, (const float4*)pw, (const float4*)f1w,
        (const float4*)f2w, (const float4*)ew, wh);

    const int MB = TOK / 128;
    for (int i = 0; i < 2; i++) {
        int sh = i;
        const float* res = (i == 0) ? x : xb;
        ln384_kernel<<<TOK / 8, 256>>>(res, yh, n1g + i * DIM, n1b + i * DIM, sh ? 2 : 1);
        gemm_fp16<<<dim3(QKVD / 128, MB), 128, GEMM_SMEM>>>(
            yh, wh + W_QKV + (size_t)i * DIM * QKVD, qkvb + i * QKVD,
            bigb, nullptr, nullptr, DIM, QKVD, 0, 0, 1);
        attn_mma_kernel<<<1024 * 12, 128>>>((const __half*)bigb, oh, rpb + i * 169 * 12, sh);
        gemm_fp16<<<dim3(DIM / 128, MB), 128, GEMM_SMEM>>>(
            oh, wh + W_PROJ + (size_t)i * DIM * DIM, pb + i * DIM,
            xb, nullptr, res, DIM, DIM, 2, sh, 0);
        ln384_kernel<<<TOK / 8, 256>>>(xb, yh, n2g + i * DIM, n2b + i * DIM, 0);
        gemm_fp16<<<dim3(FFN / 128, MB), 128, GEMM_SMEM>>>(
            yh, wh + W_FC1 + (size_t)i * DIM * FFN, f1b + i * FFN,
            bigb, nullptr, nullptr, DIM, FFN, 1, 0, 1);
        gemm_fp16<<<dim3(DIM / 128, MB), 128, GEMM_SMEM>>>(
            (const __half*)bigb, wh + W_FC2 + (size_t)i * FFN * DIM, f2b + i * DIM,
            xb, xh, xb, FFN, DIM, 3, 0, 0);
    }

    gemm_fp16<<<dim3(EXPD / 128, MB), 128, GEMM_SMEM>>>(
        xh, wh + W_EXP, nullptr, bigb, nullptr, nullptr, DIM, EXPD, 0, 0, 0);
    expand_ln_kernel<<<TOK * 4 / 8, 256>>>(bigb, (float*)d_out, eg, ebv);
}

// round 15
// speedup vs baseline: 1.1750x; 1.0163x over previous
#include <cuda_runtime.h>
#include <cuda_fp16.h>
#include <math.h>
#include <stdint.h>
#include <mma.h>
using namespace nvcuda;

// ---------------- problem constants ----------------
#define TOK   50176
#define DIM   384
#define QKVD  1152
#define FFN   1536
#define EXPD  768

// ---------------- scratch ----------------
static __device__ float  g_x  [TOK * DIM];
static __device__ __half g_xh [TOK * DIM];
static __device__ __half g_y  [TOK * DIM];
static __device__ __half g_o  [TOK * DIM];
static __device__ float  g_big[TOK * FFN];
static __device__ __half g_w  [3833856];

#define W_QKV 0
#define W_PROJ 884736
#define W_FC1 1179648
#define W_FC2 2359296
#define W_EXP 3538944

// ---------------- helpers ----------------
__device__ __forceinline__ uint32_t smem_u32(const void* p) {
    uint32_t a;
    asm("{ .reg .u64 t; cvta.to.shared.u64 t, %1; cvt.u32.u64 %0, t; }" : "=r"(a) : "l"(p));
    return a;
}
__device__ __forceinline__ void cp16(uint32_t s, const void* g) {
    asm volatile("cp.async.cg.shared.global [%0], [%1], 16;" :: "r"(s), "l"(g) : "memory");
}
#define CP_COMMIT() asm volatile("cp.async.commit_group;" ::: "memory")
#define CP_WAIT(n)  asm volatile("cp.async.wait_group %0;" :: "n"(n) : "memory")

__device__ __forceinline__ int map_row(int ridx, int shifted) {
    int n  = ridx % 49;
    int wi = (ridx / 49) & 63;
    int b  = ridx / (49 * 64);
    int r = n / 7, c = n % 7;
    int wh = wi >> 3, ww = wi & 7;
    int h = wh * 7 + r, w = ww * 7 + c;
    if (shifted) { h = (h + 3) % 56; w = (w + 3) % 56; }
    return b * 3136 + h * 56 + w;
}

__device__ __forceinline__ float warp_sum(float v) {
    #pragma unroll
    for (int o = 16; o; o >>= 1) v += __shfl_xor_sync(0xffffffffu, v, o);
    return v;
}
__device__ __forceinline__ float gelu(float v) {
    return 0.5f * v * (1.f + erff(v * 0.7071067811865476f));
}

// ---------------- fp16 wmma GEMM (round-10 config, unchanged) ----------------
#define ASTR 72
#define BSTR 136
#define A_STAGE (128 * ASTR)
#define B_STAGE (64 * BSTR)
#define STG (A_STAGE + B_STAGE)
#define OSTR 132

__global__ __launch_bounds__(128, 2)
void gemm_fp16(const __half* __restrict__ A, const __half* __restrict__ W,
               const float* __restrict__ bias, void* __restrict__ Cv,
               __half* __restrict__ mirror, const float* __restrict__ resid,
               int K, int Nc, int epilogue, int shifted, int out_half) {
    extern __shared__ __align__(16) char smraw[];
    __half* smh = (__half*)smraw;
    float*  smf = (float*)smraw;
    int tid = threadIdx.x;
    int wid = tid >> 5;
    int wm = (wid & 1) * 64;
    int wn = (wid >> 1) * 64;
    int rowBase = blockIdx.y * 128;
    int colBase = blockIdx.x * 128;
    int nk = K >> 6;

    wmma::fragment<wmma::accumulator, 16, 16, 16, float> acc[4][4];
    #pragma unroll
    for (int i = 0; i < 4; i++)
        #pragma unroll
        for (int j = 0; j < 4; j++) wmma::fill_fragment(acc[i][j], 0.f);

    #define STAGE_LOAD(kt, buf) do {                                              \
        __half* As_ = smh + (buf) * STG;                                          \
        __half* Bs_ = As_ + A_STAGE;                                              \
        uint32_t as_ = smem_u32(As_), bs_ = smem_u32(Bs_);                        \
        int kg_ = (kt) * 64;                                                      \
        _Pragma("unroll")                                                         \
        for (int l = 0; l < 8; l++) {                                             \
            int c = tid + l * 128;                                                \
            int r = c >> 3, q = (c & 7) * 8;                                      \
            cp16(as_ + (uint32_t)(r * ASTR + q) * 2,                              \
                 A + (size_t)(rowBase + r) * K + kg_ + q);                        \
            int kr = c >> 4, nq = (c & 15) * 8;                                   \
            cp16(bs_ + (uint32_t)(kr * BSTR + nq) * 2,                            \
                 W + (size_t)(kg_ + kr) * Nc + colBase + nq);                     \
        }                                                                         \
    } while (0)

    STAGE_LOAD(0, 0); CP_COMMIT();
    STAGE_LOAD(1, 1); CP_COMMIT();

    for (int kt = 0; kt < nk; kt++) {
        if (kt + 1 < nk) { CP_WAIT(1); } else { CP_WAIT(0); }
        __syncthreads();
        if (kt + 2 < nk) { STAGE_LOAD(kt + 2, (kt + 2) % 3); CP_COMMIT(); }

        const __half* As = smh + (kt % 3) * STG;
        const __half* Bs = As + A_STAGE;
        #pragma unroll
        for (int k16 = 0; k16 < 4; k16++) {
            wmma::fragment<wmma::matrix_a, 16, 16, 16, __half, wmma::row_major> af[4];
            wmma::fragment<wmma::matrix_b, 16, 16, 16, __half, wmma::row_major> bf[4];
            #pragma unroll
            for (int i = 0; i < 4; i++)
                wmma::load_matrix_sync(af[i], As + (wm + i * 16) * ASTR + k16 * 16, ASTR);
            #pragma unroll
            for (int j = 0; j < 4; j++)
                wmma::load_matrix_sync(bf[j], Bs + (k16 * 16) * BSTR + wn + j * 16, BSTR);
            #pragma unroll
            for (int i = 0; i < 4; i++)
                #pragma unroll
                for (int j = 0; j < 4; j++)
                    wmma::mma_sync(acc[i][j], af[i], bf[j], acc[i][j]);
        }
    }
    __syncthreads();

    #pragma unroll
    for (int i = 0; i < 4; i++)
        #pragma unroll
        for (int j = 0; j < 4; j++)
            wmma::store_matrix_sync(smf + (wm + i * 16) * OSTR + wn + j * 16,
                                    acc[i][j], OSTR, wmma::mem_row_major);
    __syncthreads();

    if (epilogue <= 1) {
        if (out_half) {
            __half* C = (__half*)Cv;
            #pragma unroll 4
            for (int e = 0; e < 32; e++) {
                int idx = tid + e * 128;
                int r = idx >> 5, c4 = (idx & 31) * 4;
                int gc = colBase + c4;
                float4 v = *(const float4*)(smf + r * OSTR + c4);
                if (bias) {
                    float4 bv = *(const float4*)(bias + gc);
                    v.x += bv.x; v.y += bv.y; v.z += bv.z; v.w += bv.w;
                }
                if (epilogue == 1) {
                    v.x = gelu(v.x); v.y = gelu(v.y); v.z = gelu(v.z); v.w = gelu(v.w);
                }
                __half2 h0 = __floats2half2_rn(v.x, v.y);
                __half2 h1 = __floats2half2_rn(v.z, v.w);
                __half2* cp = (__half2*)(C + (size_t)(rowBase + r) * Nc + gc);
                cp[0] = h0; cp[1] = h1;
            }
        } else {
            float* C = (float*)Cv;
            #pragma unroll 4
            for (int e = 0; e < 32; e++) {
                int idx = tid + e * 128;
                int r = idx >> 5, c4 = (idx & 31) * 4;
                int gc = colBase + c4;
                float4 v = *(const float4*)(smf + r * OSTR + c4);
                if (bias) {
                    float4 bv = *(const float4*)(bias + gc);
                    v.x += bv.x; v.y += bv.y; v.z += bv.z; v.w += bv.w;
                }
                *(float4*)(C + (size_t)(rowBase + r) * Nc + gc) = v;
            }
        }
    } else {
        float* C = (float*)Cv;
        #pragma unroll 4
        for (int e = 0; e < 32; e++) {
            int idx = tid + e * 128;
            int r = idx >> 5, c4 = (idx & 31) * 4;
            int gr = rowBase + r, gc = colBase + c4;
            float4 v = *(const float4*)(smf + r * OSTR + c4);
            float4 bv = *(const float4*)(bias + gc);
            v.x += bv.x; v.y += bv.y; v.z += bv.z; v.w += bv.w;
            int orow = (epilogue == 2) ? map_row(gr, shifted) : gr;
            size_t off = (size_t)orow * Nc + gc;
            float4 rv = *(const float4*)(resid + off);
            v.x += rv.x; v.y += rv.y; v.z += rv.z; v.w += rv.w;
            *(float4*)(C + off) = v;
            if (epilogue == 3) {
                __half2* mp = (__half2*)(mirror + off);
                mp[0] = __floats2half2_rn(v.x, v.y);
                mp[1] = __floats2half2_rn(v.z, v.w);
            }
        }
    }
}

// ---------------- fused weight fp32 -> fp16 (all 5 tensors, one launch) ----------
#define N4_QKV  221184
#define N4_PROJ 73728
#define N4_FC1  294912
#define N4_FC2  294912
#define N4_EXP  73728
#define N4_ALL  (N4_QKV + N4_PROJ + N4_FC1 + N4_FC2 + N4_EXP)

__global__ void tohalf_all(const float4* __restrict__ a0, const float4* __restrict__ a1,
                           const float4* __restrict__ a2, const float4* __restrict__ a3,
                           const float4* __restrict__ a4, __half* __restrict__ out) {
    int i = blockIdx.x * blockDim.x + threadIdx.x;
    if (i >= N4_ALL) return;
    const float4* src; int local; int off;
    if (i < N4_QKV) { src = a0; local = i; off = W_QKV; }
    else if (i < N4_QKV + N4_PROJ) { src = a1; local = i - N4_QKV; off = W_PROJ; }
    else if (i < N4_QKV + N4_PROJ + N4_FC1) { src = a2; local = i - N4_QKV - N4_PROJ; off = W_FC1; }
    else if (i < N4_QKV + N4_PROJ + N4_FC1 + N4_FC2) {
        src = a3; local = i - N4_QKV - N4_PROJ - N4_FC1; off = W_FC2;
    } else { src = a4; local = i - N4_QKV - N4_PROJ - N4_FC1 - N4_FC2; off = W_EXP; }
    float4 v = src[local];
    __half2* o = (__half2*)(out + off + local * 4);
    o[0] = __floats2half2_rn(v.x, v.y);
    o[1] = __floats2half2_rn(v.z, v.w);
}

// ---------------- LayerNorm over 384: 1 warp per row, float4 I/O ----------------
__global__ __launch_bounds__(256)
void ln384_kernel(const float* __restrict__ src, __half* __restrict__ dst,
                  const float* __restrict__ g, const float* __restrict__ b,
                  int mode) {
    int row = blockIdx.x * 8 + (threadIdx.x >> 5);
    int lane = threadIdx.x & 31;
    int t = (mode == 0) ? row : map_row(row, mode == 2);
    const float4* sp = (const float4*)(src + (size_t)t * DIM);
    float4 v[3];
    float s = 0.f;
    #pragma unroll
    for (int e = 0; e < 3; e++) {
        v[e] = sp[lane + e * 32];
        s += v[e].x + v[e].y + v[e].z + v[e].w;
    }
    float m = warp_sum(s) * (1.f / 384.f);
    float vs = 0.f;
    #pragma unroll
    for (int e = 0; e < 3; e++) {
        v[e].x -= m; v[e].y -= m; v[e].z -= m; v[e].w -= m;
        vs += v[e].x * v[e].x + v[e].y * v[e].y + v[e].z * v[e].z + v[e].w * v[e].w;
    }
    float inv = rsqrtf(warp_sum(vs) * (1.f / 384.f) + 1e-5f);
    __half* dp = dst + (size_t)row * DIM;
    #pragma unroll
    for (int e = 0; e < 3; e++) {
        int c4 = (lane + e * 32) * 4;
        float4 gv = *(const float4*)(g + c4);
        float4 bv = *(const float4*)(b + c4);
        float o0 = v[e].x * inv * gv.x + bv.x;
        float o1 = v[e].y * inv * gv.y + bv.y;
        float o2 = v[e].z * inv * gv.z + bv.z;
        float o3 = v[e].w * inv * gv.w + bv.w;
        __half2* hp = (__half2*)(dp + c4);
        hp[0] = __floats2half2_rn(o0, o1);
        hp[1] = __floats2half2_rn(o2, o3);
    }
}

// ---------------- HMMA windowed attention v4: smem-aliased phases -------------
// Byte offsets into one shared buffer:
//   [0, 5120)      qs   (64x40 half)    -- dead after QK^T
//   [5120, 10240)  ks   (64x40 half)    -- dead after QK^T
//   [0, 9216)      ps   (64x72 half)    -- written in softmax (aliases qs/ks)
//   [10240, 15360) vsm  (64x40 half)
//   [15360, 32768) ss   (64x68 float)   -- scores; reused (ld 36) for PV out
//   [32768, 33024) rsum (64 float)
//   [33024, 33536) psum (2x64 float)
//   [33536, 34212) bias (169 float)
//   [34212, 34408) lab  (49 int)
#define AT_SMEM 34432
__global__ __launch_bounds__(128)
void attn_mma_kernel(const __half* __restrict__ qkv, __half* __restrict__ o,
                     const float* __restrict__ rpb, int shifted) {
    __shared__ __align__(16) char smb[AT_SMEM];
    __half* qs   = (__half*)(smb);
    __half* ks   = (__half*)(smb + 5120);
    __half* ps   = (__half*)(smb);
    __half* vsm  = (__half*)(smb + 10240);
    float*  ss   = (float*)(smb + 15360);
    float*  rsum = (float*)(smb + 32768);
    float*  psum = (float*)(smb + 33024);   // [2][64]
    float*  bias_s = (float*)(smb + 33536);
    int*    lab_s  = (int*)(smb + 34212);

    int head = blockIdx.x % 12;
    int win  = blockIdx.x / 12;
    int wi = win & 63;
    int wh = wi >> 3, ww = wi & 7;
    int base = win * 49;
    int tid = threadIdx.x;
    int wid = tid >> 5;

    const float sc = 0.17677669529663687f;
    const __half2 z2 = __float2half2_rn(0.f);

    for (int idx = tid; idx < 169; idx += 128)
        bias_s[idx] = rpb[idx * 12 + head];
    if (tid < 49) {
        int rj = (tid * 37) >> 8, cj = tid - rj * 7;
        int hh = wh * 7 + rj, wc = ww * 7 + cj;
        int gh = hh < 49 ? 0 : (hh < 53 ? 1 : 2);
        int gw = wc < 49 ? 0 : (wc < 53 ? 1 : 2);
        lab_s[tid] = gh * 3 + gw;
    }

    for (int idx = tid; idx < 64 * 16; idx += 128) {
        int j = idx >> 4, d2 = (idx & 15) * 2;
        int off = j * 40 + d2;
        if (j < 49) {
            size_t ro = (size_t)(base + j) * QKVD + head * 32 + d2;
            __half2 qv = *(const __half2*)(qkv + ro);
            float2 qf = __half22float2(qv);
            *(__half2*)(qs + off)  = __floats2half2_rn(qf.x * sc, qf.y * sc);
            *(__half2*)(ks + off)  = *(const __half2*)(qkv + ro + 384);
            *(__half2*)(vsm + off) = *(const __half2*)(qkv + ro + 768);
        } else {
            *(__half2*)(qs + off)  = z2;
            *(__half2*)(ks + off)  = z2;
            *(__half2*)(vsm + off) = z2;
        }
    }
    for (int idx = tid; idx < 64 * 4; idx += 128) {
        int j = idx >> 2, d2 = 32 + (idx & 3) * 2;
        int off = j * 40 + d2;
        *(__half2*)(qs + off)  = z2;
        *(__half2*)(ks + off)  = z2;
        *(__half2*)(vsm + off) = z2;
    }
    __syncthreads();

    // QK^T: warp wid -> rows [16w,16w+16) x 64 cols
    {
        wmma::fragment<wmma::accumulator, 16, 16, 16, float> sacc[4];
        #pragma unroll
        for (int n = 0; n < 4; n++) wmma::fill_fragment(sacc[n], 0.f);
        #pragma unroll
        for (int k16 = 0; k16 < 2; k16++) {
            wmma::fragment<wmma::matrix_a, 16, 16, 16, __half, wmma::row_major> aq;
            wmma::load_matrix_sync(aq, qs + (wid * 16) * 40 + k16 * 16, 40);
            #pragma unroll
            for (int n = 0; n < 4; n++) {
                wmma::fragment<wmma::matrix_b, 16, 16, 16, __half, wmma::col_major> bk;
                wmma::load_matrix_sync(bk, ks + (n * 16) * 40 + k16 * 16, 40);
                wmma::mma_sync(sacc[n], aq, bk, sacc[n]);
            }
        }
        #pragma unroll
        for (int n = 0; n < 4; n++)
            wmma::store_matrix_sync(ss + (wid * 16) * 68 + n * 16, sacc[n], 68,
                                    wmma::mem_row_major);
    }
    __syncthreads();   // qs/ks reads done -> ps may overwrite them

    // softmax: 2 threads per row (j ranges [0,25) / [25,49))
    {
        int i = tid & 63;
        int hf = tid >> 6;
        if (i < 49) {
            int ri = (i * 37) >> 8, ci = i - ri * 7;
            int lab_i = lab_s[i];
            float sum = 0.f;
            int j0 = hf ? 25 : 0, j1 = hf ? 49 : 25;
            for (int j = j0; j < j1; j++) {
                int rj = (j * 37) >> 8, cj = j - rj * 7;
                float s = ss[i * 68 + j] + bias_s[(ri - rj + 6) * 13 + (ci - cj + 6)];
                if (shifted && lab_s[j] != lab_i) s -= 100.0f;
                __half eh = __float2half(__expf(s));
                ps[i * 72 + j] = eh;
                sum += __half2float(eh);
            }
            psum[hf * 64 + i] = sum;
            if (hf) {
                #pragma unroll
                for (int j = 49; j < 64; j++) ps[i * 72 + j] = __float2half(0.f);
            }
        } else {
            int j0 = hf ? 32 : 0, j1 = hf ? 64 : 32;
            for (int j = j0; j < j1; j++) ps[i * 72 + j] = __float2half(0.f);
        }
    }
    __syncthreads();
    if (tid < 64)
        rsum[tid] = (tid < 49) ? 1.0f / (psum[tid] + psum[64 + tid]) : 0.f;
    __syncthreads();

    // PV: warp wid -> rows [16w,16w+16) x 32 cols; reuse ss (ld 36)
    {
        wmma::fragment<wmma::accumulator, 16, 16, 16, float> oacc[2];
        #pragma unroll
        for (int n = 0; n < 2; n++) wmma::fill_fragment(oacc[n], 0.f);
        #pragma unroll
        for (int k16 = 0; k16 < 4; k16++) {
            wmma::fragment<wmma::matrix_a, 16, 16, 16, __half, wmma::row_major> ap;
            wmma::load_matrix_sync(ap, ps + (wid * 16) * 72 + k16 * 16, 72);
            #pragma unroll
            for (int n = 0; n < 2; n++) {
                wmma::fragment<wmma::matrix_b, 16, 16, 16, __half, wmma::row_major> bv;
                wmma::load_matrix_sync(bv, vsm + (k16 * 16) * 40 + n * 16, 40);
                wmma::mma_sync(oacc[n], ap, bv, oacc[n]);
            }
        }
        #pragma unroll
        for (int n = 0; n < 2; n++)
            wmma::store_matrix_sync(ss + (wid * 16) * 36 + n * 16, oacc[n], 36,
                                    wmma::mem_row_major);
    }
    __syncthreads();

    for (int idx = tid; idx < 49 * 16; idx += 128) {
        int i = idx >> 4, d2 = (idx & 15) * 2;
        float inv = rsum[i];
        float v0 = ss[i * 36 + d2]     * inv;
        float v1 = ss[i * 36 + d2 + 1] * inv;
        *(__half2*)(o + (size_t)(base + i) * DIM + head * 32 + d2) =
            __floats2half2_rn(v0, v1);
    }
}

// ---------------- PatchExpand pixel-shuffle + LN over 192 (half input) ----------
__global__ __launch_bounds__(256)
void expand_ln_kernel(const __half* __restrict__ e, float* __restrict__ out,
                      const float* __restrict__ g, const float* __restrict__ b) {
    int tt = blockIdx.x * 8 + (threadIdx.x >> 5);
    int lane = threadIdx.x & 31;
    int bb = tt / 12544;
    int rem = tt % 12544;
    int oh = rem / 112, ow = rem % 112;
    int h = oh >> 1, p = oh & 1, w = ow >> 1, q = ow & 1;
    int erow = bb * 3136 + h * 56 + w;
    const __half2* sp = (const __half2*)(e + (size_t)erow * EXPD + (p * 2 + q) * 192);
    float v[6];
    float s = 0.f;
    #pragma unroll
    for (int k = 0; k < 3; k++) {
        float2 f = __half22float2(sp[lane + k * 32]);
        v[k * 2] = f.x; v[k * 2 + 1] = f.y;
        s += f.x + f.y;
    }
    float m = warp_sum(s) * (1.f / 192.f);
    float vs = 0.f;
    #pragma unroll
    for (int k = 0; k < 6; k++) { v[k] -= m; vs += v[k] * v[k]; }
    float inv = rsqrtf(warp_sum(vs) * (1.f / 192.f) + 1e-5f);
    float* dp = out + (size_t)tt * 192;
    #pragma unroll
    for (int k = 0; k < 3; k++) {
        int c = (lane + k * 32) * 2;
        dp[c]     = v[k * 2]     * inv * g[c]     + b[c];
        dp[c + 1] = v[k * 2 + 1] * inv * g[c + 1] + b[c + 1];
    }
}

// ---------------- host orchestration ----------------
extern "C" void kernel_launch(void* const* d_in, const int* in_sizes, int n_in,
                              void* d_out, int out_size) {
    const float* x    = (const float*)d_in[0];
    const float* n1g  = (const float*)d_in[1];
    const float* n1b  = (const float*)d_in[2];
    const float* qkvw = (const float*)d_in[3];
    const float* qkvb = (const float*)d_in[4];
    const float* rpb  = (const float*)d_in[5];
    const float* pw   = (const float*)d_in[6];
    const float* pb   = (const float*)d_in[7];
    const float* n2g  = (const float*)d_in[8];
    const float* n2b  = (const float*)d_in[9];
    const float* f1w  = (const float*)d_in[10];
    const float* f1b  = (const float*)d_in[11];
    const float* f2w  = (const float*)d_in[12];
    const float* f2b  = (const float*)d_in[13];
    const float* ew   = (const float*)d_in[14];
    const float* eg   = (const float*)d_in[15];
    const float* ebv  = (const float*)d_in[16];

    float *xb, *bigb;
    __half *xh, *yh, *oh, *wh;
    cudaGetSymbolAddress((void**)&xb,   g_x);
    cudaGetSymbolAddress((void**)&xh,   g_xh);
    cudaGetSymbolAddress((void**)&yh,   g_y);
    cudaGetSymbolAddress((void**)&oh,   g_o);
    cudaGetSymbolAddress((void**)&bigb, g_big);
    cudaGetSymbolAddress((void**)&wh,   g_w);

    static int smem_set = 0;
    const int GEMM_SMEM = 3 * STG * sizeof(__half);   // 107520 B
    if (!smem_set) {
        cudaFuncSetAttribute(gemm_fp16,
                             cudaFuncAttributeMaxDynamicSharedMemorySize, GEMM_SMEM);
        smem_set = 1;
    }

    tohalf_all<<<(N4_ALL + 255) / 256, 256>>>(
        (const float4*)qkvw, (const float4*)pw, (const float4*)f1w,
        (const float4*)f2w, (const float4*)ew, wh);

    const int MB = TOK / 128;
    for (int i = 0; i < 2; i++) {
        int sh = i;
        const float* res = (i == 0) ? x : xb;
        ln384_kernel<<<TOK / 8, 256>>>(res, yh, n1g + i * DIM, n1b + i * DIM, sh ? 2 : 1);
        gemm_fp16<<<dim3(QKVD / 128, MB), 128, GEMM_SMEM>>>(
            yh, wh + W_QKV + (size_t)i * DIM * QKVD, qkvb + i * QKVD,
            bigb, nullptr, nullptr, DIM, QKVD, 0, 0, 1);
        attn_mma_kernel<<<1024 * 12, 128>>>((const __half*)bigb, oh, rpb + i * 169 * 12, sh);
        gemm_fp16<<<dim3(DIM / 128, MB), 128, GEMM_SMEM>>>(
            oh, wh + W_PROJ + (size_t)i * DIM * DIM, pb + i * DIM,
            xb, nullptr, res, DIM, DIM, 2, sh, 0);
        ln384_kernel<<<TOK / 8, 256>>>(xb, yh, n2g + i * DIM, n2b + i * DIM, 0);
        gemm_fp16<<<dim3(FFN / 128, MB), 128, GEMM_SMEM>>>(
            yh, wh + W_FC1 + (size_t)i * DIM * FFN, f1b + i * FFN,
            bigb, nullptr, nullptr, DIM, FFN, 1, 0, 1);
        gemm_fp16<<<dim3(DIM / 128, MB), 128, GEMM_SMEM>>>(
            (const __half*)bigb, wh + W_FC2 + (size_t)i * FFN * DIM, f2b + i * DIM,
            xb, xh, xb, FFN, DIM, 3, 0, 0);
    }

    // expand GEMM -> fp16 output; pixel-shuffle LN reads half, writes fp32 d_out
    gemm_fp16<<<dim3(EXPD / 128, MB), 128, GEMM_SMEM>>>(
        xh, wh + W_EXP, nullptr, bigb, nullptr, nullptr, DIM, EXPD, 0, 0, 1);
    expand_ln_kernel<<<TOK * 4 / 8, 256>>>((const __half*)bigb, (float*)d_out, eg, ebv);
}

// round 16
// speedup vs baseline: 1.2301x; 1.0470x over previous
#include <cuda_runtime.h>
#include <cuda_fp16.h>
#include <math.h>
#include <stdint.h>
#include <mma.h>
using namespace nvcuda;

// ---------------- problem constants ----------------
#define TOK   50176
#define DIM   384
#define QKVD  1152
#define FFN   1536
#define EXPD  768

// ---------------- scratch ----------------
static __device__ float  g_x  [TOK * DIM];
static __device__ __half g_xh [TOK * DIM];
static __device__ __half g_y  [TOK * DIM];
static __device__ __half g_o  [TOK * DIM];
static __device__ float  g_big[TOK * FFN];
static __device__ __half g_w  [3833856];

#define W_QKV 0
#define W_PROJ 884736
#define W_FC1 1179648
#define W_FC2 2359296
#define W_EXP 3538944

// ---------------- helpers ----------------
__device__ __forceinline__ uint32_t smem_u32(const void* p) {
    uint32_t a;
    asm("{ .reg .u64 t; cvta.to.shared.u64 t, %1; cvt.u32.u64 %0, t; }" : "=r"(a) : "l"(p));
    return a;
}
__device__ __forceinline__ void cp16(uint32_t s, const void* g) {
    asm volatile("cp.async.cg.shared.global [%0], [%1], 16;" :: "r"(s), "l"(g) : "memory");
}
#define CP_COMMIT() asm volatile("cp.async.commit_group;" ::: "memory")
#define CP_WAIT(n)  asm volatile("cp.async.wait_group %0;" :: "n"(n) : "memory")

__device__ __forceinline__ int map_row(int ridx, int shifted) {
    int n  = ridx % 49;
    int wi = (ridx / 49) & 63;
    int b  = ridx / (49 * 64);
    int r = n / 7, c = n % 7;
    int wh = wi >> 3, ww = wi & 7;
    int h = wh * 7 + r, w = ww * 7 + c;
    if (shifted) { h = (h + 3) % 56; w = (w + 3) % 56; }
    return b * 3136 + h * 56 + w;
}

__device__ __forceinline__ float warp_sum(float v) {
    #pragma unroll
    for (int o = 16; o; o >>= 1) v += __shfl_xor_sync(0xffffffffu, v, o);
    return v;
}
__device__ __forceinline__ float gelu(float v) {
    return 0.5f * v * (1.f + erff(v * 0.7071067811865476f));
}

// ---------------- fp16 wmma GEMM (round-10 config, unchanged) ----------------
#define ASTR 72
#define BSTR 136
#define A_STAGE (128 * ASTR)
#define B_STAGE (64 * BSTR)
#define STG (A_STAGE + B_STAGE)
#define OSTR 132

__global__ __launch_bounds__(128, 2)
void gemm_fp16(const __half* __restrict__ A, const __half* __restrict__ W,
               const float* __restrict__ bias, void* __restrict__ Cv,
               __half* __restrict__ mirror, const float* __restrict__ resid,
               int K, int Nc, int epilogue, int shifted, int out_half) {
    extern __shared__ __align__(16) char smraw[];
    __half* smh = (__half*)smraw;
    float*  smf = (float*)smraw;
    int tid = threadIdx.x;
    int wid = tid >> 5;
    int wm = (wid & 1) * 64;
    int wn = (wid >> 1) * 64;
    int rowBase = blockIdx.y * 128;
    int colBase = blockIdx.x * 128;
    int nk = K >> 6;

    wmma::fragment<wmma::accumulator, 16, 16, 16, float> acc[4][4];
    #pragma unroll
    for (int i = 0; i < 4; i++)
        #pragma unroll
        for (int j = 0; j < 4; j++) wmma::fill_fragment(acc[i][j], 0.f);

    #define STAGE_LOAD(kt, buf) do {                                              \
        __half* As_ = smh + (buf) * STG;                                          \
        __half* Bs_ = As_ + A_STAGE;                                              \
        uint32_t as_ = smem_u32(As_), bs_ = smem_u32(Bs_);                        \
        int kg_ = (kt) * 64;                                                      \
        _Pragma("unroll")                                                         \
        for (int l = 0; l < 8; l++) {                                             \
            int c = tid + l * 128;                                                \
            int r = c >> 3, q = (c & 7) * 8;                                      \
            cp16(as_ + (uint32_t)(r * ASTR + q) * 2,                              \
                 A + (size_t)(rowBase + r) * K + kg_ + q);                        \
            int kr = c >> 4, nq = (c & 15) * 8;                                   \
            cp16(bs_ + (uint32_t)(kr * BSTR + nq) * 2,                            \
                 W + (size_t)(kg_ + kr) * Nc + colBase + nq);                     \
        }                                                                         \
    } while (0)

    STAGE_LOAD(0, 0); CP_COMMIT();
    STAGE_LOAD(1, 1); CP_COMMIT();

    for (int kt = 0; kt < nk; kt++) {
        if (kt + 1 < nk) { CP_WAIT(1); } else { CP_WAIT(0); }
        __syncthreads();
        if (kt + 2 < nk) { STAGE_LOAD(kt + 2, (kt + 2) % 3); CP_COMMIT(); }

        const __half* As = smh + (kt % 3) * STG;
        const __half* Bs = As + A_STAGE;
        #pragma unroll
        for (int k16 = 0; k16 < 4; k16++) {
            wmma::fragment<wmma::matrix_a, 16, 16, 16, __half, wmma::row_major> af[4];
            wmma::fragment<wmma::matrix_b, 16, 16, 16, __half, wmma::row_major> bf[4];
            #pragma unroll
            for (int i = 0; i < 4; i++)
                wmma::load_matrix_sync(af[i], As + (wm + i * 16) * ASTR + k16 * 16, ASTR);
            #pragma unroll
            for (int j = 0; j < 4; j++)
                wmma::load_matrix_sync(bf[j], Bs + (k16 * 16) * BSTR + wn + j * 16, BSTR);
            #pragma unroll
            for (int i = 0; i < 4; i++)
                #pragma unroll
                for (int j = 0; j < 4; j++)
                    wmma::mma_sync(acc[i][j], af[i], bf[j], acc[i][j]);
        }
    }
    __syncthreads();

    #pragma unroll
    for (int i = 0; i < 4; i++)
        #pragma unroll
        for (int j = 0; j < 4; j++)
            wmma::store_matrix_sync(smf + (wm + i * 16) * OSTR + wn + j * 16,
                                    acc[i][j], OSTR, wmma::mem_row_major);
    __syncthreads();

    if (epilogue <= 1) {
        if (out_half) {
            __half* C = (__half*)Cv;
            #pragma unroll 4
            for (int e = 0; e < 32; e++) {
                int idx = tid + e * 128;
                int r = idx >> 5, c4 = (idx & 31) * 4;
                int gc = colBase + c4;
                float4 v = *(const float4*)(smf + r * OSTR + c4);
                if (bias) {
                    float4 bv = *(const float4*)(bias + gc);
                    v.x += bv.x; v.y += bv.y; v.z += bv.z; v.w += bv.w;
                }
                if (epilogue == 1) {
                    v.x = gelu(v.x); v.y = gelu(v.y); v.z = gelu(v.z); v.w = gelu(v.w);
                }
                __half2 h0 = __floats2half2_rn(v.x, v.y);
                __half2 h1 = __floats2half2_rn(v.z, v.w);
                __half2* cp = (__half2*)(C + (size_t)(rowBase + r) * Nc + gc);
                cp[0] = h0; cp[1] = h1;
            }
        } else {
            float* C = (float*)Cv;
            #pragma unroll 4
            for (int e = 0; e < 32; e++) {
                int idx = tid + e * 128;
                int r = idx >> 5, c4 = (idx & 31) * 4;
                int gc = colBase + c4;
                float4 v = *(const float4*)(smf + r * OSTR + c4);
                if (bias) {
                    float4 bv = *(const float4*)(bias + gc);
                    v.x += bv.x; v.y += bv.y; v.z += bv.z; v.w += bv.w;
                }
                *(float4*)(C + (size_t)(rowBase + r) * Nc + gc) = v;
            }
        }
    } else {
        float* C = (float*)Cv;
        #pragma unroll 4
        for (int e = 0; e < 32; e++) {
            int idx = tid + e * 128;
            int r = idx >> 5, c4 = (idx & 31) * 4;
            int gr = rowBase + r, gc = colBase + c4;
            float4 v = *(const float4*)(smf + r * OSTR + c4);
            float4 bv = *(const float4*)(bias + gc);
            v.x += bv.x; v.y += bv.y; v.z += bv.z; v.w += bv.w;
            int orow = (epilogue == 2) ? map_row(gr, shifted) : gr;
            size_t off = (size_t)orow * Nc + gc;
            float4 rv = *(const float4*)(resid + off);
            v.x += rv.x; v.y += rv.y; v.z += rv.z; v.w += rv.w;
            *(float4*)(C + off) = v;
            if (epilogue == 3) {
                __half2* mp = (__half2*)(mirror + off);
                mp[0] = __floats2half2_rn(v.x, v.y);
                mp[1] = __floats2half2_rn(v.z, v.w);
            }
        }
    }
}

// ---------------- fused weight fp32 -> fp16 (all 5 tensors, one launch) ----------
#define N4_QKV  221184
#define N4_PROJ 73728
#define N4_FC1  294912
#define N4_FC2  294912
#define N4_EXP  73728
#define N4_ALL  (N4_QKV + N4_PROJ + N4_FC1 + N4_FC2 + N4_EXP)

__global__ void tohalf_all(const float4* __restrict__ a0, const float4* __restrict__ a1,
                           const float4* __restrict__ a2, const float4* __restrict__ a3,
                           const float4* __restrict__ a4, __half* __restrict__ out) {
    int i = blockIdx.x * blockDim.x + threadIdx.x;
    if (i >= N4_ALL) return;
    const float4* src; int local; int off;
    if (i < N4_QKV) { src = a0; local = i; off = W_QKV; }
    else if (i < N4_QKV + N4_PROJ) { src = a1; local = i - N4_QKV; off = W_PROJ; }
    else if (i < N4_QKV + N4_PROJ + N4_FC1) { src = a2; local = i - N4_QKV - N4_PROJ; off = W_FC1; }
    else if (i < N4_QKV + N4_PROJ + N4_FC1 + N4_FC2) {
        src = a3; local = i - N4_QKV - N4_PROJ - N4_FC1; off = W_FC2;
    } else { src = a4; local = i - N4_QKV - N4_PROJ - N4_FC1 - N4_FC2; off = W_EXP; }
    float4 v = src[local];
    __half2* o = (__half2*)(out + off + local * 4);
    o[0] = __floats2half2_rn(v.x, v.y);
    o[1] = __floats2half2_rn(v.z, v.w);
}

// ---------------- LayerNorm over 384: 1 warp per row, float4 I/O ----------------
__global__ __launch_bounds__(256)
void ln384_kernel(const float* __restrict__ src, __half* __restrict__ dst,
                  const float* __restrict__ g, const float* __restrict__ b,
                  int mode) {
    int row = blockIdx.x * 8 + (threadIdx.x >> 5);
    int lane = threadIdx.x & 31;
    int t = (mode == 0) ? row : map_row(row, mode == 2);
    const float4* sp = (const float4*)(src + (size_t)t * DIM);
    float4 v[3];
    float s = 0.f;
    #pragma unroll
    for (int e = 0; e < 3; e++) {
        v[e] = sp[lane + e * 32];
        s += v[e].x + v[e].y + v[e].z + v[e].w;
    }
    float m = warp_sum(s) * (1.f / 384.f);
    float vs = 0.f;
    #pragma unroll
    for (int e = 0; e < 3; e++) {
        v[e].x -= m; v[e].y -= m; v[e].z -= m; v[e].w -= m;
        vs += v[e].x * v[e].x + v[e].y * v[e].y + v[e].z * v[e].z + v[e].w * v[e].w;
    }
    float inv = rsqrtf(warp_sum(vs) * (1.f / 384.f) + 1e-5f);
    __half* dp = dst + (size_t)row * DIM;
    #pragma unroll
    for (int e = 0; e < 3; e++) {
        int c4 = (lane + e * 32) * 4;
        float4 gv = *(const float4*)(g + c4);
        float4 bv = *(const float4*)(b + c4);
        float o0 = v[e].x * inv * gv.x + bv.x;
        float o1 = v[e].y * inv * gv.y + bv.y;
        float o2 = v[e].z * inv * gv.z + bv.z;
        float o3 = v[e].w * inv * gv.w + bv.w;
        __half2* hp = (__half2*)(dp + c4);
        hp[0] = __floats2half2_rn(o0, o1);
        hp[1] = __floats2half2_rn(o2, o3);
    }
}

// ---------------- HMMA windowed attention v5: cp.async loads, scale in softmax --
// smem layout (bytes):
//   [0, 5120)      qs   (64x40 half)   -- dead after QK^T
//   [5120, 10240)  ks   (64x40 half)   -- dead after QK^T
//   [0, 9216)      ps   (64x72 half)   -- aliases qs/ks after QK^T
//   [10240, 15360) vsm  (64x40 half)
//   [15360, 32768) ss   (64x68 float)  -- scores; reused (ld 36) for PV out
//   [32768, 33024) rsum (64 float)
//   [33024, 33536) psum (2x64 float)
//   [33536, 34212) bias (169 float)
//   [34212, 34408) lab  (49 int)
#define AT_SMEM 34432
__global__ __launch_bounds__(128)
void attn_mma_kernel(const __half* __restrict__ qkv, __half* __restrict__ o,
                     const float* __restrict__ rpb, int shifted) {
    __shared__ __align__(16) char smb[AT_SMEM];
    __half* qs   = (__half*)(smb);
    __half* ks   = (__half*)(smb + 5120);
    __half* ps   = (__half*)(smb);
    __half* vsm  = (__half*)(smb + 10240);
    float*  ss   = (float*)(smb + 15360);
    float*  rsum = (float*)(smb + 32768);
    float*  psum = (float*)(smb + 33024);
    float*  bias_s = (float*)(smb + 33536);
    int*    lab_s  = (int*)(smb + 34212);

    int head = blockIdx.x % 12;
    int win  = blockIdx.x / 12;
    int wi = win & 63;
    int wh = wi >> 3, ww = wi & 7;
    int base = win * 49;
    int tid = threadIdx.x;
    int wid = tid >> 5;

    const float sc = 0.17677669529663687f;
    uint32_t sq = smem_u32(qs), sk = smem_u32(ks), sv = smem_u32(vsm);

    // zero pad regions only (disjoint from cp.async destinations)
    {
        const float4 z4 = make_float4(0.f, 0.f, 0.f, 0.f);
        // column pads: bytes [64,80) of each of 64 rows, 3 tensors
        for (int idx = tid; idx < 64 * 3; idx += 128) {
            int tens = idx >> 6, j = idx & 63;
            char* dst = smb + tens * 5120 + j * 80 + 64;
            *(float4*)dst = z4;
        }
        // row pads: rows 49..63, bytes [0,64), 3 tensors (15*4 chunks each)
        for (int idx = tid; idx < 180; idx += 128) {
            int tens = idx / 60, r = idx % 60;
            int j = 49 + (r >> 2), c = r & 3;
            char* dst = smb + tens * 5120 + j * 80 + c * 16;
            *(float4*)dst = z4;
        }
    }

    // cp.async q/k/v: 49 rows x 4 x 16B each
    for (int idx = tid; idx < 196; idx += 128) {
        int j = idx >> 2, c = idx & 3;
        size_t ro = (size_t)(base + j) * QKVD + head * 32 + c * 8;
        uint32_t doff = (uint32_t)(j * 80 + c * 16);
        cp16(sq + doff, qkv + ro);
        cp16(sk + doff, qkv + ro + 384);
        cp16(sv + doff, qkv + ro + 768);
    }
    CP_COMMIT();

    // bias table + mask labels (overlap with async copies)
    for (int idx = tid; idx < 169; idx += 128)
        bias_s[idx] = rpb[idx * 12 + head];
    if (tid < 49) {
        int rj = (tid * 37) >> 8, cj = tid - rj * 7;
        int hh = wh * 7 + rj, wc = ww * 7 + cj;
        int gh = hh < 49 ? 0 : (hh < 53 ? 1 : 2);
        int gw = wc < 49 ? 0 : (wc < 53 ? 1 : 2);
        lab_s[tid] = gh * 3 + gw;
    }
    CP_WAIT(0);
    __syncthreads();

    // QK^T: warp wid -> rows [16w,16w+16) x 64 cols  (raw q, scale applied later)
    {
        wmma::fragment<wmma::accumulator, 16, 16, 16, float> sacc[4];
        #pragma unroll
        for (int n = 0; n < 4; n++) wmma::fill_fragment(sacc[n], 0.f);
        #pragma unroll
        for (int k16 = 0; k16 < 2; k16++) {
            wmma::fragment<wmma::matrix_a, 16, 16, 16, __half, wmma::row_major> aq;
            wmma::load_matrix_sync(aq, qs + (wid * 16) * 40 + k16 * 16, 40);
            #pragma unroll
            for (int n = 0; n < 4; n++) {
                wmma::fragment<wmma::matrix_b, 16, 16, 16, __half, wmma::col_major> bk;
                wmma::load_matrix_sync(bk, ks + (n * 16) * 40 + k16 * 16, 40);
                wmma::mma_sync(sacc[n], aq, bk, sacc[n]);
            }
        }
        #pragma unroll
        for (int n = 0; n < 4; n++)
            wmma::store_matrix_sync(ss + (wid * 16) * 68 + n * 16, sacc[n], 68,
                                    wmma::mem_row_major);
    }
    __syncthreads();   // qs/ks reads done -> ps may overwrite them

    // softmax: 2 threads per row; s = score*sc + bias
    {
        int i = tid & 63;
        int hf = tid >> 6;
        if (i < 49) {
            int ri = (i * 37) >> 8, ci = i - ri * 7;
            int lab_i = lab_s[i];
            float sum = 0.f;
            int j0 = hf ? 25 : 0, j1 = hf ? 49 : 25;
            for (int j = j0; j < j1; j++) {
                int rj = (j * 37) >> 8, cj = j - rj * 7;
                float s = fmaf(ss[i * 68 + j], sc,
                               bias_s[(ri - rj + 6) * 13 + (ci - cj + 6)]);
                if (shifted && lab_s[j] != lab_i) s -= 100.0f;
                __half eh = __float2half(__expf(s));
                ps[i * 72 + j] = eh;
                sum += __half2float(eh);
            }
            psum[hf * 64 + i] = sum;
            if (hf) {
                #pragma unroll
                for (int j = 49; j < 64; j++) ps[i * 72 + j] = __float2half(0.f);
            }
        } else {
            int j0 = hf ? 32 : 0, j1 = hf ? 64 : 32;
            for (int j = j0; j < j1; j++) ps[i * 72 + j] = __float2half(0.f);
        }
    }
    __syncthreads();
    if (tid < 64)
        rsum[tid] = (tid < 49) ? 1.0f / (psum[tid] + psum[64 + tid]) : 0.f;
    __syncthreads();

    // PV: warp wid -> rows [16w,16w+16) x 32 cols; reuse ss (ld 36)
    {
        wmma::fragment<wmma::accumulator, 16, 16, 16, float> oacc[2];
        #pragma unroll
        for (int n = 0; n < 2; n++) wmma::fill_fragment(oacc[n], 0.f);
        #pragma unroll
        for (int k16 = 0; k16 < 4; k16++) {
            wmma::fragment<wmma::matrix_a, 16, 16, 16, __half, wmma::row_major> ap;
            wmma::load_matrix_sync(ap, ps + (wid * 16) * 72 + k16 * 16, 72);
            #pragma unroll
            for (int n = 0; n < 2; n++) {
                wmma::fragment<wmma::matrix_b, 16, 16, 16, __half, wmma::row_major> bv;
                wmma::load_matrix_sync(bv, vsm + (k16 * 16) * 40 + n * 16, 40);
                wmma::mma_sync(oacc[n], ap, bv, oacc[n]);
            }
        }
        #pragma unroll
        for (int n = 0; n < 2; n++)
            wmma::store_matrix_sync(ss + (wid * 16) * 36 + n * 16, oacc[n], 36,
                                    wmma::mem_row_major);
    }
    __syncthreads();

    for (int idx = tid; idx < 49 * 16; idx += 128) {
        int i = idx >> 4, d2 = (idx & 15) * 2;
        float inv = rsum[i];
        float v0 = ss[i * 36 + d2]     * inv;
        float v1 = ss[i * 36 + d2 + 1] * inv;
        *(__half2*)(o + (size_t)(base + i) * DIM + head * 32 + d2) =
            __floats2half2_rn(v0, v1);
    }
}

// ---------------- PatchExpand pixel-shuffle + LN over 192 (half input) ----------
__global__ __launch_bounds__(256)
void expand_ln_kernel(const __half* __restrict__ e, float* __restrict__ out,
                      const float* __restrict__ g, const float* __restrict__ b) {
    int tt = blockIdx.x * 8 + (threadIdx.x >> 5);
    int lane = threadIdx.x & 31;
    int bb = tt / 12544;
    int rem = tt % 12544;
    int oh = rem / 112, ow = rem % 112;
    int h = oh >> 1, p = oh & 1, w = ow >> 1, q = ow & 1;
    int erow = bb * 3136 + h * 56 + w;
    const __half2* sp = (const __half2*)(e + (size_t)erow * EXPD + (p * 2 + q) * 192);
    float v[6];
    float s = 0.f;
    #pragma unroll
    for (int k = 0; k < 3; k++) {
        float2 f = __half22float2(sp[lane + k * 32]);
        v[k * 2] = f.x; v[k * 2 + 1] = f.y;
        s += f.x + f.y;
    }
    float m = warp_sum(s) * (1.f / 192.f);
    float vs = 0.f;
    #pragma unroll
    for (int k = 0; k < 6; k++) { v[k] -= m; vs += v[k] * v[k]; }
    float inv = rsqrtf(warp_sum(vs) * (1.f / 192.f) + 1e-5f);
    float* dp = out + (size_t)tt * 192;
    #pragma unroll
    for (int k = 0; k < 3; k++) {
        int c = (lane + k * 32) * 2;
        dp[c]     = v[k * 2]     * inv * g[c]     + b[c];
        dp[c + 1] = v[k * 2 + 1] * inv * g[c + 1] + b[c + 1];
    }
}

// ---------------- host orchestration ----------------
extern "C" void kernel_launch(void* const* d_in, const int* in_sizes, int n_in,
                              void* d_out, int out_size) {
    const float* x    = (const float*)d_in[0];
    const float* n1g  = (const float*)d_in[1];
    const float* n1b  = (const float*)d_in[2];
    const float* qkvw = (const float*)d_in[3];
    const float* qkvb = (const float*)d_in[4];
    const float* rpb  = (const float*)d_in[5];
    const float* pw   = (const float*)d_in[6];
    const float* pb   = (const float*)d_in[7];
    const float* n2g  = (const float*)d_in[8];
    const float* n2b  = (const float*)d_in[9];
    const float* f1w  = (const float*)d_in[10];
    const float* f1b  = (const float*)d_in[11];
    const float* f2w  = (const float*)d_in[12];
    const float* f2b  = (const float*)d_in[13];
    const float* ew   = (const float*)d_in[14];
    const float* eg   = (const float*)d_in[15];
    const float* ebv  = (const float*)d_in[16];

    float *xb, *bigb;
    __half *xh, *yh, *oh, *wh;
    cudaGetSymbolAddress((void**)&xb,   g_x);
    cudaGetSymbolAddress((void**)&xh,   g_xh);
    cudaGetSymbolAddress((void**)&yh,   g_y);
    cudaGetSymbolAddress((void**)&oh,   g_o);
    cudaGetSymbolAddress((void**)&bigb, g_big);
    cudaGetSymbolAddress((void**)&wh,   g_w);

    static int smem_set = 0;
    const int GEMM_SMEM = 3 * STG * sizeof(__half);   // 107520 B
    if (!smem_set) {
        cudaFuncSetAttribute(gemm_fp16,
                             cudaFuncAttributeMaxDynamicSharedMemorySize, GEMM_SMEM);
        smem_set = 1;
    }

    tohalf_all<<<(N4_ALL + 255) / 256, 256>>>(
        (const float4*)qkvw, (const float4*)pw, (const float4*)f1w,
        (const float4*)f2w, (const float4*)ew, wh);

    const int MB = TOK / 128;
    for (int i = 0; i < 2; i++) {
        int sh = i;
        const float* res = (i == 0) ? x : xb;
        ln384_kernel<<<TOK / 8, 256>>>(res, yh, n1g + i * DIM, n1b + i * DIM, sh ? 2 : 1);
        gemm_fp16<<<dim3(QKVD / 128, MB), 128, GEMM_SMEM>>>(
            yh, wh + W_QKV + (size_t)i * DIM * QKVD, qkvb + i * QKVD,
            bigb, nullptr, nullptr, DIM, QKVD, 0, 0, 1);
        attn_mma_kernel<<<1024 * 12, 128>>>((const __half*)bigb, oh, rpb + i * 169 * 12, sh);
        gemm_fp16<<<dim3(DIM / 128, MB), 128, GEMM_SMEM>>>(
            oh, wh + W_PROJ + (size_t)i * DIM * DIM, pb + i * DIM,
            xb, nullptr, res, DIM, DIM, 2, sh, 0);
        ln384_kernel<<<TOK / 8, 256>>>(xb, yh, n2g + i * DIM, n2b + i * DIM, 0);
        gemm_fp16<<<dim3(FFN / 128, MB), 128, GEMM_SMEM>>>(
            yh, wh + W_FC1 + (size_t)i * DIM * FFN, f1b + i * FFN,
            bigb, nullptr, nullptr, DIM, FFN, 1, 0, 1);
        gemm_fp16<<<dim3(DIM / 128, MB), 128, GEMM_SMEM>>>(
            (const __half*)bigb, wh + W_FC2 + (size_t)i * FFN * DIM, f2b + i * DIM,
            xb, xh, xb, FFN, DIM, 3, 0, 0);
    }

    gemm_fp16<<<dim3(EXPD / 128, MB), 128, GEMM_SMEM>>>(
        xh, wh + W_EXP, nullptr, bigb, nullptr, nullptr, DIM, EXPD, 0, 0, 1);
    expand_ln_kernel<<<TOK * 4 / 8, 256>>>((const __half*)bigb, (float*)d_out, eg, ebv);
}

// round 17
// speedup vs baseline: 1.2369x; 1.0055x over previous
#include <cuda_runtime.h>
#include <cuda_fp16.h>
#include <math.h>
#include <stdint.h>
#include <mma.h>
using namespace nvcuda;

// ---------------- problem constants ----------------
#define TOK   50176
#define DIM   384
#define QKVD  1152
#define FFN   1536
#define EXPD  768

// ---------------- scratch ----------------
static __device__ float  g_x  [TOK * DIM];
static __device__ __half g_xh [TOK * DIM];
static __device__ __half g_y  [TOK * DIM];
static __device__ __half g_o  [TOK * DIM];
static __device__ float  g_big[TOK * FFN];
static __device__ __half g_w  [3833856];

#define W_QKV 0
#define W_PROJ 884736
#define W_FC1 1179648
#define W_FC2 2359296
#define W_EXP 3538944

// ---------------- helpers ----------------
__device__ __forceinline__ uint32_t smem_u32(const void* p) {
    uint32_t a;
    asm("{ .reg .u64 t; cvta.to.shared.u64 t, %1; cvt.u32.u64 %0, t; }" : "=r"(a) : "l"(p));
    return a;
}
__device__ __forceinline__ void cp16(uint32_t s, const void* g) {
    asm volatile("cp.async.cg.shared.global [%0], [%1], 16;" :: "r"(s), "l"(g) : "memory");
}
#define CP_COMMIT() asm volatile("cp.async.commit_group;" ::: "memory")
#define CP_WAIT(n)  asm volatile("cp.async.wait_group %0;" :: "n"(n) : "memory")

__device__ __forceinline__ int map_row(int ridx, int shifted) {
    int n  = ridx % 49;
    int wi = (ridx / 49) & 63;
    int b  = ridx / (49 * 64);
    int r = n / 7, c = n % 7;
    int wh = wi >> 3, ww = wi & 7;
    int h = wh * 7 + r, w = ww * 7 + c;
    if (shifted) { h = (h + 3) % 56; w = (w + 3) % 56; }
    return b * 3136 + h * 56 + w;
}

__device__ __forceinline__ float warp_sum(float v) {
    #pragma unroll
    for (int o = 16; o; o >>= 1) v += __shfl_xor_sync(0xffffffffu, v, o);
    return v;
}
__device__ __forceinline__ float gelu(float v) {
    return 0.5f * v * (1.f + erff(v * 0.7071067811865476f));
}

// ---------------- fp16 wmma GEMM (round-10 config, unchanged) ----------------
#define ASTR 72
#define BSTR 136
#define A_STAGE (128 * ASTR)
#define B_STAGE (64 * BSTR)
#define STG (A_STAGE + B_STAGE)
#define OSTR 132

__global__ __launch_bounds__(128, 2)
void gemm_fp16(const __half* __restrict__ A, const __half* __restrict__ W,
               const float* __restrict__ bias, void* __restrict__ Cv,
               __half* __restrict__ mirror, const float* __restrict__ resid,
               int K, int Nc, int epilogue, int shifted, int out_half) {
    extern __shared__ __align__(16) char smraw[];
    __half* smh = (__half*)smraw;
    float*  smf = (float*)smraw;
    int tid = threadIdx.x;
    int wid = tid >> 5;
    int wm = (wid & 1) * 64;
    int wn = (wid >> 1) * 64;
    int rowBase = blockIdx.y * 128;
    int colBase = blockIdx.x * 128;
    int nk = K >> 6;

    wmma::fragment<wmma::accumulator, 16, 16, 16, float> acc[4][4];
    #pragma unroll
    for (int i = 0; i < 4; i++)
        #pragma unroll
        for (int j = 0; j < 4; j++) wmma::fill_fragment(acc[i][j], 0.f);

    #define STAGE_LOAD(kt, buf) do {                                              \
        __half* As_ = smh + (buf) * STG;                                          \
        __half* Bs_ = As_ + A_STAGE;                                              \
        uint32_t as_ = smem_u32(As_), bs_ = smem_u32(Bs_);                        \
        int kg_ = (kt) * 64;                                                      \
        _Pragma("unroll")                                                         \
        for (int l = 0; l < 8; l++) {                                             \
            int c = tid + l * 128;                                                \
            int r = c >> 3, q = (c & 7) * 8;                                      \
            cp16(as_ + (uint32_t)(r * ASTR + q) * 2,                              \
                 A + (size_t)(rowBase + r) * K + kg_ + q);                        \
            int kr = c >> 4, nq = (c & 15) * 8;                                   \
            cp16(bs_ + (uint32_t)(kr * BSTR + nq) * 2,                            \
                 W + (size_t)(kg_ + kr) * Nc + colBase + nq);                     \
        }                                                                         \
    } while (0)

    STAGE_LOAD(0, 0); CP_COMMIT();
    STAGE_LOAD(1, 1); CP_COMMIT();

    for (int kt = 0; kt < nk; kt++) {
        if (kt + 1 < nk) { CP_WAIT(1); } else { CP_WAIT(0); }
        __syncthreads();
        if (kt + 2 < nk) { STAGE_LOAD(kt + 2, (kt + 2) % 3); CP_COMMIT(); }

        const __half* As = smh + (kt % 3) * STG;
        const __half* Bs = As + A_STAGE;
        #pragma unroll
        for (int k16 = 0; k16 < 4; k16++) {
            wmma::fragment<wmma::matrix_a, 16, 16, 16, __half, wmma::row_major> af[4];
            wmma::fragment<wmma::matrix_b, 16, 16, 16, __half, wmma::row_major> bf[4];
            #pragma unroll
            for (int i = 0; i < 4; i++)
                wmma::load_matrix_sync(af[i], As + (wm + i * 16) * ASTR + k16 * 16, ASTR);
            #pragma unroll
            for (int j = 0; j < 4; j++)
                wmma::load_matrix_sync(bf[j], Bs + (k16 * 16) * BSTR + wn + j * 16, BSTR);
            #pragma unroll
            for (int i = 0; i < 4; i++)
                #pragma unroll
                for (int j = 0; j < 4; j++)
                    wmma::mma_sync(acc[i][j], af[i], bf[j], acc[i][j]);
        }
    }
    __syncthreads();

    #pragma unroll
    for (int i = 0; i < 4; i++)
        #pragma unroll
        for (int j = 0; j < 4; j++)
            wmma::store_matrix_sync(smf + (wm + i * 16) * OSTR + wn + j * 16,
                                    acc[i][j], OSTR, wmma::mem_row_major);
    __syncthreads();

    if (epilogue <= 1) {
        if (out_half) {
            __half* C = (__half*)Cv;
            #pragma unroll 4
            for (int e = 0; e < 32; e++) {
                int idx = tid + e * 128;
                int r = idx >> 5, c4 = (idx & 31) * 4;
                int gc = colBase + c4;
                float4 v = *(const float4*)(smf + r * OSTR + c4);
                if (bias) {
                    float4 bv = *(const float4*)(bias + gc);
                    v.x += bv.x; v.y += bv.y; v.z += bv.z; v.w += bv.w;
                }
                if (epilogue == 1) {
                    v.x = gelu(v.x); v.y = gelu(v.y); v.z = gelu(v.z); v.w = gelu(v.w);
                }
                __half2 h0 = __floats2half2_rn(v.x, v.y);
                __half2 h1 = __floats2half2_rn(v.z, v.w);
                __half2* cp = (__half2*)(C + (size_t)(rowBase + r) * Nc + gc);
                cp[0] = h0; cp[1] = h1;
            }
        } else {
            float* C = (float*)Cv;
            #pragma unroll 4
            for (int e = 0; e < 32; e++) {
                int idx = tid + e * 128;
                int r = idx >> 5, c4 = (idx & 31) * 4;
                int gc = colBase + c4;
                float4 v = *(const float4*)(smf + r * OSTR + c4);
                if (bias) {
                    float4 bv = *(const float4*)(bias + gc);
                    v.x += bv.x; v.y += bv.y; v.z += bv.z; v.w += bv.w;
                }
                *(float4*)(C + (size_t)(rowBase + r) * Nc + gc) = v;
            }
        }
    } else {
        float* C = (float*)Cv;
        #pragma unroll 4
        for (int e = 0; e < 32; e++) {
            int idx = tid + e * 128;
            int r = idx >> 5, c4 = (idx & 31) * 4;
            int gr = rowBase + r, gc = colBase + c4;
            float4 v = *(const float4*)(smf + r * OSTR + c4);
            float4 bv = *(const float4*)(bias + gc);
            v.x += bv.x; v.y += bv.y; v.z += bv.z; v.w += bv.w;
            int orow = (epilogue == 2) ? map_row(gr, shifted) : gr;
            size_t off = (size_t)orow * Nc + gc;
            float4 rv = *(const float4*)(resid + off);
            v.x += rv.x; v.y += rv.y; v.z += rv.z; v.w += rv.w;
            *(float4*)(C + off) = v;
            if (epilogue == 3) {
                __half2* mp = (__half2*)(mirror + off);
                mp[0] = __floats2half2_rn(v.x, v.y);
                mp[1] = __floats2half2_rn(v.z, v.w);
            }
        }
    }
}

// ---------------- fused weight fp32 -> fp16 (all 5 tensors, one launch) ----------
#define N4_QKV  221184
#define N4_PROJ 73728
#define N4_FC1  294912
#define N4_FC2  294912
#define N4_EXP  73728
#define N4_ALL  (N4_QKV + N4_PROJ + N4_FC1 + N4_FC2 + N4_EXP)

__global__ void tohalf_all(const float4* __restrict__ a0, const float4* __restrict__ a1,
                           const float4* __restrict__ a2, const float4* __restrict__ a3,
                           const float4* __restrict__ a4, __half* __restrict__ out) {
    int i = blockIdx.x * blockDim.x + threadIdx.x;
    if (i >= N4_ALL) return;
    const float4* src; int local; int off;
    if (i < N4_QKV) { src = a0; local = i; off = W_QKV; }
    else if (i < N4_QKV + N4_PROJ) { src = a1; local = i - N4_QKV; off = W_PROJ; }
    else if (i < N4_QKV + N4_PROJ + N4_FC1) { src = a2; local = i - N4_QKV - N4_PROJ; off = W_FC1; }
    else if (i < N4_QKV + N4_PROJ + N4_FC1 + N4_FC2) {
        src = a3; local = i - N4_QKV - N4_PROJ - N4_FC1; off = W_FC2;
    } else { src = a4; local = i - N4_QKV - N4_PROJ - N4_FC1 - N4_FC2; off = W_EXP; }
    float4 v = src[local];
    __half2* o = (__half2*)(out + off + local * 4);
    o[0] = __floats2half2_rn(v.x, v.y);
    o[1] = __floats2half2_rn(v.z, v.w);
}

// ---------------- LayerNorm over 384: 1 warp per row, float4 I/O ----------------
__global__ __launch_bounds__(256)
void ln384_kernel(const float* __restrict__ src, __half* __restrict__ dst,
                  const float* __restrict__ g, const float* __restrict__ b,
                  int mode) {
    int row = blockIdx.x * 8 + (threadIdx.x >> 5);
    int lane = threadIdx.x & 31;
    int t = (mode == 0) ? row : map_row(row, mode == 2);
    const float4* sp = (const float4*)(src + (size_t)t * DIM);
    float4 v[3];
    float s = 0.f;
    #pragma unroll
    for (int e = 0; e < 3; e++) {
        v[e] = sp[lane + e * 32];
        s += v[e].x + v[e].y + v[e].z + v[e].w;
    }
    float m = warp_sum(s) * (1.f / 384.f);
    float vs = 0.f;
    #pragma unroll
    for (int e = 0; e < 3; e++) {
        v[e].x -= m; v[e].y -= m; v[e].z -= m; v[e].w -= m;
        vs += v[e].x * v[e].x + v[e].y * v[e].y + v[e].z * v[e].z + v[e].w * v[e].w;
    }
    float inv = rsqrtf(warp_sum(vs) * (1.f / 384.f) + 1e-5f);
    __half* dp = dst + (size_t)row * DIM;
    #pragma unroll
    for (int e = 0; e < 3; e++) {
        int c4 = (lane + e * 32) * 4;
        float4 gv = *(const float4*)(g + c4);
        float4 bv = *(const float4*)(b + c4);
        float o0 = v[e].x * inv * gv.x + bv.x;
        float o1 = v[e].y * inv * gv.y + bv.y;
        float o2 = v[e].z * inv * gv.z + bv.z;
        float o3 = v[e].w * inv * gv.w + bv.w;
        __half2* hp = (__half2*)(dp + c4);
        hp[0] = __floats2half2_rn(o0, o1);
        hp[1] = __floats2half2_rn(o2, o3);
    }
}

// ---------------- HMMA windowed attention v6: packed smem (7 CTA/SM), vector IO --
// smem layout (bytes):
//   [0, 5120)       qs   (64x40 half)   -- dead after QK^T
//   [5120, 10240)   ks   (64x40 half)   -- dead after QK^T
//   [0, 9216)       ps   (64x72 half)   -- aliases qs/ks after QK^T
//   [9216, 9728)    psum (2x64 float)   -- in ps-region slack (written post-QK^T)
//   [9728, 9984)    rsum (64 float)     -- in ps-region slack
//   [10240, 15360)  vsm  (64x40 half)
//   [15360, 32256)  ss   (64x66 float)  -- scores; reused (ld 36) for PV out
//   [32256, 32932)  bias (169 float)
//   [32932, 33128)  lab  (49 int)
#define AT_SMEM 33152
__global__ __launch_bounds__(128)
void attn_mma_kernel(const __half* __restrict__ qkv, __half* __restrict__ o,
                     const float* __restrict__ rpb, int shifted) {
    __shared__ __align__(16) char smb[AT_SMEM];
    __half* qs   = (__half*)(smb);
    __half* ks   = (__half*)(smb + 5120);
    __half* ps   = (__half*)(smb);
    float*  psum = (float*)(smb + 9216);
    float*  rsum = (float*)(smb + 9728);
    __half* vsm  = (__half*)(smb + 10240);
    float*  ss   = (float*)(smb + 15360);
    float*  bias_s = (float*)(smb + 32256);
    int*    lab_s  = (int*)(smb + 32932);

    int head = blockIdx.x % 12;
    int win  = blockIdx.x / 12;
    int wi = win & 63;
    int wh = wi >> 3, ww = wi & 7;
    int base = win * 49;
    int tid = threadIdx.x;
    int wid = tid >> 5;

    const float sc = 0.17677669529663687f;
    uint32_t sq = smem_u32(qs), sk = smem_u32(ks), sv = smem_u32(vsm);

    // zero pad regions only (disjoint from cp.async destinations)
    {
        const float4 z4 = make_float4(0.f, 0.f, 0.f, 0.f);
        for (int idx = tid; idx < 64 * 3; idx += 128) {
            int tens = idx >> 6, j = idx & 63;
            char* dst = smb + ((tens == 2) ? 10240 : tens * 5120) + j * 80 + 64;
            *(float4*)dst = z4;
        }
        for (int idx = tid; idx < 180; idx += 128) {
            int tens = idx / 60, r = idx % 60;
            int j = 49 + (r >> 2), c = r & 3;
            char* dst = smb + ((tens == 2) ? 10240 : tens * 5120) + j * 80 + c * 16;
            *(float4*)dst = z4;
        }
    }

    // cp.async q/k/v: 49 rows x 4 x 16B each
    for (int idx = tid; idx < 196; idx += 128) {
        int j = idx >> 2, c = idx & 3;
        size_t ro = (size_t)(base + j) * QKVD + head * 32 + c * 8;
        uint32_t doff = (uint32_t)(j * 80 + c * 16);
        cp16(sq + doff, qkv + ro);
        cp16(sk + doff, qkv + ro + 384);
        cp16(sv + doff, qkv + ro + 768);
    }
    CP_COMMIT();

    for (int idx = tid; idx < 169; idx += 128)
        bias_s[idx] = rpb[idx * 12 + head];
    if (tid < 49) {
        int rj = (tid * 37) >> 8, cj = tid - rj * 7;
        int hh = wh * 7 + rj, wc = ww * 7 + cj;
        int gh = hh < 49 ? 0 : (hh < 53 ? 1 : 2);
        int gw = wc < 49 ? 0 : (wc < 53 ? 1 : 2);
        lab_s[tid] = gh * 3 + gw;
    }
    CP_WAIT(0);
    __syncthreads();

    // QK^T: warp wid -> rows [16w,16w+16) x 64 cols (raw q; scale later)
    {
        wmma::fragment<wmma::accumulator, 16, 16, 16, float> sacc[4];
        #pragma unroll
        for (int n = 0; n < 4; n++) wmma::fill_fragment(sacc[n], 0.f);
        #pragma unroll
        for (int k16 = 0; k16 < 2; k16++) {
            wmma::fragment<wmma::matrix_a, 16, 16, 16, __half, wmma::row_major> aq;
            wmma::load_matrix_sync(aq, qs + (wid * 16) * 40 + k16 * 16, 40);
            #pragma unroll
            for (int n = 0; n < 4; n++) {
                wmma::fragment<wmma::matrix_b, 16, 16, 16, __half, wmma::col_major> bk;
                wmma::load_matrix_sync(bk, ks + (n * 16) * 40 + k16 * 16, 40);
                wmma::mma_sync(sacc[n], aq, bk, sacc[n]);
            }
        }
        #pragma unroll
        for (int n = 0; n < 4; n++)
            wmma::store_matrix_sync(ss + (wid * 16) * 66 + n * 16, sacc[n], 66,
                                    wmma::mem_row_major);
    }
    __syncthreads();   // qs/ks dead -> ps/psum/rsum regions usable

    // softmax: 2 threads per row, vectorized (hf=0: j 0..23, hf=1: j 24..48)
    {
        int i = tid & 63;
        int hf = tid >> 6;
        if (i < 49) {
            int ri = (i * 37) >> 8, ci = i - ri * 7;
            int lab_i = lab_s[i];
            float sum = 0.f;
            int j0 = hf ? 24 : 0, j1 = hf ? 48 : 24;
            for (int j = j0; j < j1; j += 2) {
                float2 sv2 = *(const float2*)(ss + i * 66 + j);
                int rj0 = (j * 37) >> 8,       cj0 = j - rj0 * 7;
                int rj1 = ((j + 1) * 37) >> 8, cj1 = j + 1 - rj1 * 7;
                float s0 = fmaf(sv2.x, sc, bias_s[(ri - rj0 + 6) * 13 + (ci - cj0 + 6)]);
                float s1 = fmaf(sv2.y, sc, bias_s[(ri - rj1 + 6) * 13 + (ci - cj1 + 6)]);
                if (shifted) {
                    if (lab_s[j]     != lab_i) s0 -= 100.0f;
                    if (lab_s[j + 1] != lab_i) s1 -= 100.0f;
                }
                __half2 eh = __floats2half2_rn(__expf(s0), __expf(s1));
                *(__half2*)(ps + i * 72 + j) = eh;
                float2 ef = __half22float2(eh);
                sum += ef.x + ef.y;
            }
            if (hf) {   // j = 48
                float s = fmaf(ss[i * 66 + 48], sc,
                               bias_s[(ri - 6) * 13 + ci]);   // rj=6, cj=6
                if (shifted && lab_s[48] != lab_i) s -= 100.0f;
                __half eh = __float2half(__expf(s));
                ps[i * 72 + 48] = eh;
                sum += __half2float(eh);
                // zero pad cols 49..63 (odd start: one scalar then half2)
                ps[i * 72 + 49] = __float2half(0.f);
                #pragma unroll
                for (int j = 50; j < 64; j += 2)
                    *(__half2*)(ps + i * 72 + j) = __float2half2_rn(0.f);
            }
            psum[hf * 64 + i] = sum;
        } else {
            const __half2 z2 = __float2half2_rn(0.f);
            int j0 = hf ? 32 : 0, j1 = hf ? 64 : 32;
            #pragma unroll
            for (int j = j0; j < j1; j += 2)
                *(__half2*)(ps + i * 72 + j) = z2;
        }
    }
    __syncthreads();
    if (tid < 64)
        rsum[tid] = (tid < 49) ? 1.0f / (psum[tid] + psum[64 + tid]) : 0.f;
    __syncthreads();

    // PV: warp wid -> rows [16w,16w+16) x 32 cols; reuse ss (ld 36)
    {
        wmma::fragment<wmma::accumulator, 16, 16, 16, float> oacc[2];
        #pragma unroll
        for (int n = 0; n < 2; n++) wmma::fill_fragment(oacc[n], 0.f);
        #pragma unroll
        for (int k16 = 0; k16 < 4; k16++) {
            wmma::fragment<wmma::matrix_a, 16, 16, 16, __half, wmma::row_major> ap;
            wmma::load_matrix_sync(ap, ps + (wid * 16) * 72 + k16 * 16, 72);
            #pragma unroll
            for (int n = 0; n < 2; n++) {
                wmma::fragment<wmma::matrix_b, 16, 16, 16, __half, wmma::row_major> bv;
                wmma::load_matrix_sync(bv, vsm + (k16 * 16) * 40 + n * 16, 40);
                wmma::mma_sync(oacc[n], ap, bv, oacc[n]);
            }
        }
        #pragma unroll
        for (int n = 0; n < 2; n++)
            wmma::store_matrix_sync(ss + (wid * 16) * 36 + n * 16, oacc[n], 36,
                                    wmma::mem_row_major);
    }
    __syncthreads();

    // epilogue: 8B stores (4 halves per iteration)
    for (int idx = tid; idx < 49 * 8; idx += 128) {
        int i = idx >> 3, d4 = (idx & 7) * 4;
        float inv = rsum[i];
        float4 v = *(const float4*)(ss + i * 36 + d4);
        __half2 h0 = __floats2half2_rn(v.x * inv, v.y * inv);
        __half2 h1 = __floats2half2_rn(v.z * inv, v.w * inv);
        uint2 pk = make_uint2(*(uint32_t*)&h0, *(uint32_t*)&h1);
        *(uint2*)(o + (size_t)(base + i) * DIM + head * 32 + d4) = pk;
    }
}

// ---------------- PatchExpand pixel-shuffle + LN over 192 (half input) ----------
__global__ __launch_bounds__(256)
void expand_ln_kernel(const __half* __restrict__ e, float* __restrict__ out,
                      const float* __restrict__ g, const float* __restrict__ b) {
    int tt = blockIdx.x * 8 + (threadIdx.x >> 5);
    int lane = threadIdx.x & 31;
    int bb = tt / 12544;
    int rem = tt % 12544;
    int oh = rem / 112, ow = rem % 112;
    int h = oh >> 1, p = oh & 1, w = ow >> 1, q = ow & 1;
    int erow = bb * 3136 + h * 56 + w;
    const __half2* sp = (const __half2*)(e + (size_t)erow * EXPD + (p * 2 + q) * 192);
    float v[6];
    float s = 0.f;
    #pragma unroll
    for (int k = 0; k < 3; k++) {
        float2 f = __half22float2(sp[lane + k * 32]);
        v[k * 2] = f.x; v[k * 2 + 1] = f.y;
        s += f.x + f.y;
    }
    float m = warp_sum(s) * (1.f / 192.f);
    float vs = 0.f;
    #pragma unroll
    for (int k = 0; k < 6; k++) { v[k] -= m; vs += v[k] * v[k]; }
    float inv = rsqrtf(warp_sum(vs) * (1.f / 192.f) + 1e-5f);
    float* dp = out + (size_t)tt * 192;
    #pragma unroll
    for (int k = 0; k < 3; k++) {
        int c = (lane + k * 32) * 2;
        dp[c]     = v[k * 2]     * inv * g[c]     + b[c];
        dp[c + 1] = v[k * 2 + 1] * inv * g[c + 1] + b[c + 1];
    }
}

// ---------------- host orchestration ----------------
extern "C" void kernel_launch(void* const* d_in, const int* in_sizes, int n_in,
                              void* d_out, int out_size) {
    const float* x    = (const float*)d_in[0];
    const float* n1g  = (const float*)d_in[1];
    const float* n1b  = (const float*)d_in[2];
    const float* qkvw = (const float*)d_in[3];
    const float* qkvb = (const float*)d_in[4];
    const float* rpb  = (const float*)d_in[5];
    const float* pw   = (const float*)d_in[6];
    const float* pb   = (const float*)d_in[7];
    const float* n2g  = (const float*)d_in[8];
    const float* n2b  = (const float*)d_in[9];
    const float* f1w  = (const float*)d_in[10];
    const float* f1b  = (const float*)d_in[11];
    const float* f2w  = (const float*)d_in[12];
    const float* f2b  = (const float*)d_in[13];
    const float* ew   = (const float*)d_in[14];
    const float* eg   = (const float*)d_in[15];
    const float* ebv  = (const float*)d_in[16];

    float *xb, *bigb;
    __half *xh, *yh, *oh, *wh;
    cudaGetSymbolAddress((void**)&xb,   g_x);
    cudaGetSymbolAddress((void**)&xh,   g_xh);
    cudaGetSymbolAddress((void**)&yh,   g_y);
    cudaGetSymbolAddress((void**)&oh,   g_o);
    cudaGetSymbolAddress((void**)&bigb, g_big);
    cudaGetSymbolAddress((void**)&wh,   g_w);

    static int smem_set = 0;
    const int GEMM_SMEM = 3 * STG * sizeof(__half);   // 107520 B
    if (!smem_set) {
        cudaFuncSetAttribute(gemm_fp16,
                             cudaFuncAttributeMaxDynamicSharedMemorySize, GEMM_SMEM);
        smem_set = 1;
    }

    tohalf_all<<<(N4_ALL + 255) / 256, 256>>>(
        (const float4*)qkvw, (const float4*)pw, (const float4*)f1w,
        (const float4*)f2w, (const float4*)ew, wh);

    const int MB = TOK / 128;
    for (int i = 0; i < 2; i++) {
        int sh = i;
        const float* res = (i == 0) ? x : xb;
        ln384_kernel<<<TOK / 8, 256>>>(res, yh, n1g + i * DIM, n1b + i * DIM, sh ? 2 : 1);
        gemm_fp16<<<dim3(QKVD / 128, MB), 128, GEMM_SMEM>>>(
            yh, wh + W_QKV + (size_t)i * DIM * QKVD, qkvb + i * QKVD,
            bigb, nullptr, nullptr, DIM, QKVD, 0, 0, 1);
        attn_mma_kernel<<<1024 * 12, 128>>>((const __half*)bigb, oh, rpb + i * 169 * 12, sh);
        gemm_fp16<<<dim3(DIM / 128, MB), 128, GEMM_SMEM>>>(
            oh, wh + W_PROJ + (size_t)i * DIM * DIM, pb + i * DIM,
            xb, nullptr, res, DIM, DIM, 2, sh, 0);
        ln384_kernel<<<TOK / 8, 256>>>(xb, yh, n2g + i * DIM, n2b + i * DIM, 0);
        gemm_fp16<<<dim3(FFN / 128, MB), 128, GEMM_SMEM>>>(
            yh, wh + W_FC1 + (size_t)i * DIM * FFN, f1b + i * FFN,
            bigb, nullptr, nullptr, DIM, FFN, 1, 0, 1);
        gemm_fp16<<<dim3(DIM / 128, MB), 128, GEMM_SMEM>>>(
            (const __half*)bigb, wh + W_FC2 + (size_t)i * FFN * DIM, f2b + i * DIM,
            xb, xh, xb, FFN, DIM, 3, 0, 0);
    }

    gemm_fp16<<<dim3(EXPD / 128, MB), 128, GEMM_SMEM>>>(
        xh, wh + W_EXP, nullptr, bigb, nullptr, nullptr, DIM, EXPD, 0, 0, 1);
    expand_ln_kernel<<<TOK * 4 / 8, 256>>>((const __half*)bigb, (float*)d_out, eg, ebv);
}